// round 4
// baseline (speedup 1.0000x reference)
#include <cuda_runtime.h>
#include <string.h>

#define NVOX 65536
#define KTAP 27
#define CH   64
#define VOXB 128          // voxels per conv block
#define TPB  256
#define EPSV 1e-5f
#define GSPITCH 65        // padded gs row (floats) -> conflict-free column reads

// ---------------- scratch (no allocations allowed) ----------------
__device__ float g_h[NVOX * CH];          // conv output buffer (h1, then h2)
__device__ float g_a[NVOX * CH];          // BN+ReLU'd activations (conv2 input)
__device__ float g_part[64 * 2 * CH];     // per-block partial sums [64][{sum,sumsq}][64]
__device__ float g_sb[2 * CH];            // folded BN affine: scale[64], bias[64]

// ---------------- packed f32x2 helpers ----------------
__device__ __forceinline__ unsigned long long pack2(float v) {
    unsigned long long r;
    asm("mov.b64 %0, {%1, %1};" : "=l"(r) : "r"(__float_as_uint(v)));
    return r;
}
__device__ __forceinline__ void fma2(unsigned long long& a,
                                     unsigned long long x, unsigned long long y) {
    asm("fma.rn.f32x2 %0, %1, %2, %0;" : "+l"(a) : "l"(x), "l"(y));
}

// ---------------- conv: out[n,d] = sum_k sum_c g[n,k,c] * W[k,c,d] ----------------
// Block: 256 threads. h = t>>7 selects channel half [32h,32h+32); v = t&127 is the
// voxel within the 128-voxel tile. A warp holds 32 consecutive voxels of one half:
//   - W reads are warp-uniform broadcasts (LDS.128, 1 phase each)
//   - gs column reads are conflict-free (pitch 65)
// Accumulators: 16x f32x2 = 32 output channels, FMAs issued as fma.rn.f32x2.
__global__ void __launch_bounds__(TPB) conv_kernel(
    const float* __restrict__ feats, const int* __restrict__ nbr,
    const float* __restrict__ W, float* __restrict__ out)
{
    extern __shared__ float smem[];
    float* gs = smem;                    // [VOXB][GSPITCH]
    float* ws = smem + VOXB * GSPITCH;   // [64][64], 16B-aligned (33280 % 16 == 0)

    const int t  = threadIdx.x;
    const int h  = t >> 7;               // 0 or 1
    const int v  = t & 127;
    const int hb = h * 32;
    const int v0 = blockIdx.x * VOXB;

    unsigned long long acc[16];
#pragma unroll
    for (int m = 0; m < 16; ++m) acc[m] = 0ull;

    const float* gsrow = gs + v * GSPITCH;

    for (int k = 0; k < KTAP; ++k) {
        __syncthreads();   // protect ws/gs reuse from previous tap's compute

        // stage W[k] (4096 floats) cooperatively: 256 threads x 4 float4
        {
            const float4* Wk  = reinterpret_cast<const float4*>(W + k * CH * CH);
            float4*       ws4 = reinterpret_cast<float4*>(ws);
#pragma unroll
            for (int i = 0; i < 4; ++i)
                ws4[t + i * TPB] = Wk[t + i * TPB];
        }

        // gather this thread's half-row (zeros for inactive taps)
        {
            const int idx = nbr[(v0 + v) * KTAP + k];
            float* d = gs + v * GSPITCH + hb;
            if (idx >= 0) {
                const float4* src =
                    reinterpret_cast<const float4*>(feats + (size_t)idx * CH + hb);
#pragma unroll
                for (int j = 0; j < 8; ++j) {
                    float4 r = src[j];
                    d[4 * j + 0] = r.x; d[4 * j + 1] = r.y;
                    d[4 * j + 2] = r.z; d[4 * j + 3] = r.w;
                }
            } else {
#pragma unroll
                for (int j = 0; j < 32; ++j) d[j] = 0.0f;
            }
        }
        __syncthreads();

        // dense contraction over input channels
#pragma unroll 4
        for (int c = 0; c < CH; ++c) {
            const unsigned long long g2 = pack2(gsrow[c]);
            const ulonglong2* wrow =
                reinterpret_cast<const ulonglong2*>(ws + c * CH + hb);
#pragma unroll
            for (int j = 0; j < 8; ++j) {
                ulonglong2 w2 = wrow[j];
                fma2(acc[2 * j + 0], g2, w2.x);
                fma2(acc[2 * j + 1], g2, w2.y);
            }
        }
    }

    // write 32 output channels
    float* op = out + (size_t)(v0 + v) * CH + hb;
#pragma unroll
    for (int j = 0; j < 8; ++j) {
        float2 u0, u1;
        memcpy(&u0, &acc[2 * j + 0], 8);
        memcpy(&u1, &acc[2 * j + 1], 8);
        reinterpret_cast<float4*>(op)[j] = make_float4(u0.x, u0.y, u1.x, u1.y);
    }
}

// ---------------- per-channel stats: block-partial sums (no atomics) ----------------
__global__ void stats_kernel(const float* __restrict__ hbuf, float* __restrict__ part)
{
    __shared__ float sh[4][2][CH];
    const int t  = threadIdx.x;
    const int c  = t & 63;
    const int rg = t >> 6;                 // 4 row groups
    const int base = blockIdx.x * 1024;    // 64 blocks x 1024 rows = 65536

    float s = 0.0f, s2 = 0.0f;
    for (int r = rg; r < 1024; r += 4) {
        float vv = hbuf[(size_t)(base + r) * CH + c];
        s += vv; s2 += vv * vv;
    }
    sh[rg][0][c] = s;
    sh[rg][1][c] = s2;
    __syncthreads();
    if (t < 128) {
        const int cc = t & 63, which = t >> 6;
        float tot = sh[0][which][cc] + sh[1][which][cc] +
                    sh[2][which][cc] + sh[3][which][cc];
        part[blockIdx.x * 128 + which * CH + cc] = tot;
    }
}

// ---------------- fold BN into per-channel affine: a = h*scale + bias ----------------
__global__ void finalize_kernel(const float* __restrict__ part,
                                const float* __restrict__ gamma,
                                const float* __restrict__ beta,
                                float* __restrict__ sb)
{
    const int c = threadIdx.x;   // 64 threads
    float s = 0.0f, s2 = 0.0f;
    for (int b = 0; b < 64; ++b) {
        s  += part[b * 128 + c];
        s2 += part[b * 128 + CH + c];
    }
    const float inv_n = 1.0f / (float)NVOX;
    const float mean  = s * inv_n;
    const float var   = s2 * inv_n - mean * mean;
    const float rstd  = rsqrtf(var + EPSV);
    const float sc    = gamma[c] * rstd;
    sb[c]      = sc;
    sb[CH + c] = beta[c] - mean * sc;
}

// ---------------- elementwise: a = relu(h*scale + bias) ----------------
__global__ void bnrelu_kernel(const float* __restrict__ hin,
                              const float* __restrict__ sb,
                              float* __restrict__ aout)
{
    const int i  = blockIdx.x * blockDim.x + threadIdx.x;   // float4 index
    const int c0 = (i * 4) & 63;
    float4 vv = reinterpret_cast<const float4*>(hin)[i];
    float4 sc = reinterpret_cast<const float4*>(sb)[c0 >> 2];
    float4 bs = reinterpret_cast<const float4*>(sb + CH)[c0 >> 2];
    float4 o;
    o.x = fmaxf(fmaf(vv.x, sc.x, bs.x), 0.0f);
    o.y = fmaxf(fmaf(vv.y, sc.y, bs.y), 0.0f);
    o.z = fmaxf(fmaf(vv.z, sc.z, bs.z), 0.0f);
    o.w = fmaxf(fmaf(vv.w, sc.w, bs.w), 0.0f);
    reinterpret_cast<float4*>(aout)[i] = o;
}

// ---------------- elementwise: out = relu(h*scale + bias + x) ----------------
__global__ void final_kernel(const float* __restrict__ hin,
                             const float* __restrict__ sb,
                             const float* __restrict__ x,
                             float* __restrict__ out)
{
    const int i  = blockIdx.x * blockDim.x + threadIdx.x;
    const int c0 = (i * 4) & 63;
    float4 vv = reinterpret_cast<const float4*>(hin)[i];
    float4 xx = reinterpret_cast<const float4*>(x)[i];
    float4 sc = reinterpret_cast<const float4*>(sb)[c0 >> 2];
    float4 bs = reinterpret_cast<const float4*>(sb + CH)[c0 >> 2];
    float4 o;
    o.x = fmaxf(fmaf(vv.x, sc.x, bs.x) + xx.x, 0.0f);
    o.y = fmaxf(fmaf(vv.y, sc.y, bs.y) + xx.y, 0.0f);
    o.z = fmaxf(fmaf(vv.z, sc.z, bs.z) + xx.z, 0.0f);
    o.w = fmaxf(fmaf(vv.w, sc.w, bs.w) + xx.w, 0.0f);
    reinterpret_cast<float4*>(out)[i] = o;
}

// ---------------- launch ----------------
extern "C" void kernel_launch(void* const* d_in, const int* in_sizes, int n_in,
                              void* d_out, int out_size)
{
    const float* x   = (const float*)d_in[0];
    const int*   nbr = (const int*)  d_in[1];
    const float* W1  = (const float*)d_in[2];
    const float* ga1 = (const float*)d_in[3];
    const float* be1 = (const float*)d_in[4];
    const float* W2  = (const float*)d_in[5];
    const float* ga2 = (const float*)d_in[6];
    const float* be2 = (const float*)d_in[7];
    float* out = (float*)d_out;

    void *ph, *pa, *pp, *ps;
    cudaGetSymbolAddress(&ph, g_h);
    cudaGetSymbolAddress(&pa, g_a);
    cudaGetSymbolAddress(&pp, g_part);
    cudaGetSymbolAddress(&ps, g_sb);
    float* hbuf = (float*)ph;
    float* abuf = (float*)pa;
    float* part = (float*)pp;
    float* sb   = (float*)ps;

    const int smem_bytes = (VOXB * GSPITCH + CH * CH) * (int)sizeof(float); // 49664
    cudaFuncSetAttribute(conv_kernel, cudaFuncAttributeMaxDynamicSharedMemorySize,
                         smem_bytes);

    const int conv_grid = NVOX / VOXB;               // 512
    const int ew_grid   = (NVOX * CH / 4) / TPB;     // 4096

    // h1 = conv(x, W1); a1 = relu(bn1(h1))
    conv_kernel<<<conv_grid, TPB, smem_bytes>>>(x, nbr, W1, hbuf);
    stats_kernel<<<64, TPB>>>(hbuf, part);
    finalize_kernel<<<1, CH>>>(part, ga1, be1, sb);
    bnrelu_kernel<<<ew_grid, TPB>>>(hbuf, sb, abuf);

    // h2 = conv(a1, W2); out = relu(bn2(h2) + x)
    conv_kernel<<<conv_grid, TPB, smem_bytes>>>(abuf, nbr, W2, hbuf);
    stats_kernel<<<64, TPB>>>(hbuf, part);
    finalize_kernel<<<1, CH>>>(part, ga2, be2, sb);
    final_kernel<<<ew_grid, TPB>>>(hbuf, sb, x, out);
}

// round 7
// speedup vs baseline: 2.4456x; 2.4456x over previous
#include <cuda_runtime.h>
#include <cuda_bf16.h>
#include <stdint.h>

#define NVOX 65536
#define KTAP 27
#define CH   64
#define TPB  256
#define EPSV 1e-5f

// ---- SMEM buffer layout (per pipeline buffer), 144B row pitch ----
#define PITCH   144
#define OFF_AHI 0
#define OFF_ALO 18432              // 128 rows * 144
#define OFF_WHI 36864
#define OFF_WLO 46080              // + 64 rows * 144
#define BUFSZ   55296
#define SMEM_TOTAL (2 * BUFSZ)     // 110592 B

// ---------------- scratch (no allocations allowed) ----------------
__device__ float          g_h[NVOX * CH];                // conv output (fp32)
__device__ __nv_bfloat16  g_xhi[NVOX * CH];
__device__ __nv_bfloat16  g_xlo[NVOX * CH];
__device__ __nv_bfloat16  g_ahi[NVOX * CH];
__device__ __nv_bfloat16  g_alo[NVOX * CH];
__device__ __nv_bfloat16  g_wthi[2 * KTAP * CH * CH];    // W^T hi: [w][k][d][c]
__device__ __nv_bfloat16  g_wtlo[2 * KTAP * CH * CH];    // W^T lo
__device__ float          g_part[64 * 2 * CH];
__device__ float          g_sb[2 * CH];

// ================= PTX helpers (all base-target legal) =================
__device__ __forceinline__ uint32_t smem_u32(const void* p) {
    uint32_t a;
    asm("{ .reg .u64 t; cvta.to.shared.u64 t, %1; cvt.u32.u64 %0, t; }"
        : "=r"(a) : "l"(p));
    return a;
}
__device__ __forceinline__ void cpa16(uint32_t dst, const void* src, uint32_t srcsz) {
    asm volatile("cp.async.ca.shared.global [%0], [%1], 16, %2;"
                 :: "r"(dst), "l"(src), "r"(srcsz) : "memory");
}
#define CPA_COMMIT() asm volatile("cp.async.commit_group;" ::: "memory")
#define CPA_WAIT1()  asm volatile("cp.async.wait_group 1;" ::: "memory")
#define CPA_WAIT0()  asm volatile("cp.async.wait_group 0;" ::: "memory")

#define LDSM4(r0, r1, r2, r3, addr) \
    asm volatile("ldmatrix.sync.aligned.m8n8.x4.shared.b16 {%0,%1,%2,%3}, [%4];" \
                 : "=r"(r0), "=r"(r1), "=r"(r2), "=r"(r3) : "r"(addr))

#define MMA16816(c, a, b0, b1) \
    asm volatile("mma.sync.aligned.m16n8k16.row.col.f32.bf16.bf16.f32 " \
                 "{%0,%1,%2,%3}, {%4,%5,%6,%7}, {%8,%9}, {%0,%1,%2,%3};" \
                 : "+f"((c)[0]), "+f"((c)[1]), "+f"((c)[2]), "+f"((c)[3]) \
                 : "r"((a)[0]), "r"((a)[1]), "r"((a)[2]), "r"((a)[3]), \
                   "r"(b0), "r"(b1))

// ================= conv via mma.sync bf16 (3-product split) =================
// CTA: 128 threads / 4 warps, one 128-voxel tile, full N=64.
// Warp w owns rows [w*32, w*32+32) = 2 m16 tiles x 8 n8 tiles, fp32 accum in regs.
// Per tap: cp.async-staged gathered A rows (hi/lo, zfill inactive) + W^T[k] (hi/lo),
// double buffered; D += Ahi*Whi + Ahi*Wlo + Alo*Whi.
__global__ void __launch_bounds__(128)
conv_mma_kernel(const __nv_bfloat16* __restrict__ fhi,
                const __nv_bfloat16* __restrict__ flo,
                const int* __restrict__ nbr,
                const __nv_bfloat16* __restrict__ wthi,
                const __nv_bfloat16* __restrict__ wtlo,
                float* __restrict__ out)
{
    extern __shared__ char smem[];
    const uint32_t sbase = smem_u32(smem);
    const int tid  = threadIdx.x;
    const int wid  = tid >> 5, lane = tid & 31;
    const int v0   = blockIdx.x * 128;
    const int rsub = tid >> 3;            // 0..15
    const int chnk = tid & 7;             // 0..7 (16B chunk within 128B row)

    // ---- stage tap k into buffer b (cp.async, zero-fill inactive taps) ----
    auto stage = [&](int b, int k) {
        const uint32_t base = sbase + (uint32_t)b * BUFSZ;
        // A: 128 rows x 128B, hi + lo
#pragma unroll
        for (int i = 0; i < 8; ++i) {
            const int row = rsub + i * 16;
            const int idx = nbr[(v0 + row) * KTAP + k];
            const uint32_t sz = (idx >= 0) ? 16u : 0u;
            const int ic = (idx >= 0) ? idx : 0;
            const char* sh = (const char*)fhi + (size_t)ic * 128 + chnk * 16;
            const char* sl = (const char*)flo + (size_t)ic * 128 + chnk * 16;
            const uint32_t d = base + OFF_AHI + (uint32_t)(row * PITCH + chnk * 16);
            cpa16(d, sh, sz);
            cpa16(d + (OFF_ALO - OFF_AHI), sl, sz);
        }
        // W^T[k]: 64 rows x 128B, hi + lo
        const char* whs = (const char*)wthi + (size_t)k * 8192;
        const char* wls = (const char*)wtlo + (size_t)k * 8192;
#pragma unroll
        for (int i = 0; i < 4; ++i) {
            const int row = rsub + i * 16;            // 0..63
            const uint32_t d = base + OFF_WHI + (uint32_t)(row * PITCH + chnk * 16);
            cpa16(d, whs + row * 128 + chnk * 16, 16);
            cpa16(d + (OFF_WLO - OFF_WHI), wls + row * 128 + chnk * 16, 16);
        }
    };

    float acc[2][8][4];
#pragma unroll
    for (int mt = 0; mt < 2; ++mt)
#pragma unroll
        for (int nt = 0; nt < 8; ++nt)
#pragma unroll
            for (int r = 0; r < 4; ++r) acc[mt][nt][r] = 0.0f;

    // ldmatrix lane->address offsets
    // A (m16k16, x4): lanes 0-7 rows m0..7 klo | 8-15 m8..15 klo | 16-23 m0..7 khi | 24-31 m8..15 khi
    const uint32_t a_loff = (uint32_t)((wid * 32 + (lane & 15)) * PITCH + (lane >> 4) * 16);
    // B (k16n8 pairs, x4): g=lane>>3: {n+r klo | n+r khi | n+8+r klo | n+8+r khi}
    const int g = lane >> 3;
    const uint32_t b_loff = (uint32_t)((((g >> 1) * 8) + (lane & 7)) * PITCH + (g & 1) * 16);

    stage(0, 0);
    CPA_COMMIT();

    for (int k = 0; k < KTAP; ++k) {
        const int b = k & 1;
        if (k + 1 < KTAP) { stage(b ^ 1, k + 1); CPA_COMMIT(); CPA_WAIT1(); }
        else              { CPA_WAIT0(); }
        __syncthreads();                       // tap k staged & visible

        const uint32_t base = sbase + (uint32_t)b * BUFSZ;
#pragma unroll
        for (int ks = 0; ks < 4; ++ks) {
            uint32_t ah[2][4], al[2][4];
#pragma unroll
            for (int mt = 0; mt < 2; ++mt) {
                const uint32_t aaddr = base + OFF_AHI + a_loff
                                     + (uint32_t)(mt * 16 * PITCH + ks * 32);
                LDSM4(ah[mt][0], ah[mt][1], ah[mt][2], ah[mt][3], aaddr);
                LDSM4(al[mt][0], al[mt][1], al[mt][2], al[mt][3],
                      aaddr + (OFF_ALO - OFF_AHI));
            }
#pragma unroll
            for (int nt2 = 0; nt2 < 4; ++nt2) {
                const uint32_t baddr = base + OFF_WHI + b_loff
                                     + (uint32_t)(nt2 * 16 * PITCH + ks * 32);
                uint32_t bh[4], bl[4];
                LDSM4(bh[0], bh[1], bh[2], bh[3], baddr);
                LDSM4(bl[0], bl[1], bl[2], bl[3], baddr + (OFF_WLO - OFF_WHI));
#pragma unroll
                for (int mt = 0; mt < 2; ++mt) {
                    MMA16816(acc[mt][nt2 * 2 + 0], ah[mt], bh[0], bh[1]);
                    MMA16816(acc[mt][nt2 * 2 + 1], ah[mt], bh[2], bh[3]);
                    MMA16816(acc[mt][nt2 * 2 + 0], ah[mt], bl[0], bl[1]);
                    MMA16816(acc[mt][nt2 * 2 + 1], ah[mt], bl[2], bl[3]);
                    MMA16816(acc[mt][nt2 * 2 + 0], al[mt], bh[0], bh[1]);
                    MMA16816(acc[mt][nt2 * 2 + 1], al[mt], bh[2], bh[3]);
                }
            }
        }
        __syncthreads();                       // all warps done with buf b
    }

    // epilogue: c-frag m16n8 -> gmem. lane: rows (lane>>2), +8; cols (lane&3)*2,+1
    const int r0 = v0 + wid * 32 + (lane >> 2);
    const int c0 = (lane & 3) * 2;
#pragma unroll
    for (int mt = 0; mt < 2; ++mt)
#pragma unroll
        for (int nt = 0; nt < 8; ++nt) {
            float* p0 = out + (size_t)(r0 + mt * 16) * CH + nt * 8 + c0;
            float* p1 = p0 + 8 * CH;
            *reinterpret_cast<float2*>(p0) = make_float2(acc[mt][nt][0], acc[mt][nt][1]);
            *reinterpret_cast<float2*>(p1) = make_float2(acc[mt][nt][2], acc[mt][nt][3]);
        }
}

// ================= prep / BN / elementwise kernels =================
__device__ __forceinline__ void split1(float v, __nv_bfloat16& h, __nv_bfloat16& l) {
    h = __float2bfloat16_rn(v);
    l = __float2bfloat16_rn(v - __bfloat162float(h));
}

__global__ void split_x_kernel(const float* __restrict__ x,
                               __nv_bfloat16* __restrict__ xhi,
                               __nv_bfloat16* __restrict__ xlo)
{
    const int i = blockIdx.x * blockDim.x + threadIdx.x;
    float4 v = reinterpret_cast<const float4*>(x)[i];
    __nv_bfloat16 h[4], l[4];
    split1(v.x, h[0], l[0]); split1(v.y, h[1], l[1]);
    split1(v.z, h[2], l[2]); split1(v.w, h[3], l[3]);
    reinterpret_cast<uint2*>(xhi)[i] = *reinterpret_cast<uint2*>(h);
    reinterpret_cast<uint2*>(xlo)[i] = *reinterpret_cast<uint2*>(l);
}

// Wt[w][k][d][c] = split(W_w[k][c][d])  (c contiguous -> [n][k] rows for ldmatrix)
__global__ void split_w_kernel(const float* __restrict__ W1,
                               const float* __restrict__ W2,
                               __nv_bfloat16* __restrict__ wthi,
                               __nv_bfloat16* __restrict__ wtlo)
{
    const int t = blockIdx.x * blockDim.x + threadIdx.x;
    const int widx = t / (KTAP * CH * CH);
    const int rem  = t % (KTAP * CH * CH);
    const int k = rem / (CH * CH);
    const int d = (rem % (CH * CH)) / CH;
    const int c = rem % CH;
    const float* W = widx ? W2 : W1;
    __nv_bfloat16 h, l;
    split1(W[k * CH * CH + c * CH + d], h, l);
    wthi[t] = h; wtlo[t] = l;
}

__global__ void stats_kernel(const float* __restrict__ hbuf, float* __restrict__ part)
{
    __shared__ float sh[4][2][CH];
    const int t = threadIdx.x, c = t & 63, rg = t >> 6;
    const int base = blockIdx.x * 1024;
    float s = 0.0f, s2 = 0.0f;
    for (int r = rg; r < 1024; r += 4) {
        float vv = hbuf[(size_t)(base + r) * CH + c];
        s += vv; s2 += vv * vv;
    }
    sh[rg][0][c] = s; sh[rg][1][c] = s2;
    __syncthreads();
    if (t < 128) {
        const int cc = t & 63, which = t >> 6;
        part[blockIdx.x * 128 + which * CH + cc] =
            sh[0][which][cc] + sh[1][which][cc] + sh[2][which][cc] + sh[3][which][cc];
    }
}

__global__ void finalize_kernel(const float* __restrict__ part,
                                const float* __restrict__ gamma,
                                const float* __restrict__ beta,
                                float* __restrict__ sbuf)
{
    const int c = threadIdx.x;
    float s = 0.0f, s2 = 0.0f;
    for (int b = 0; b < 64; ++b) {
        s  += part[b * 128 + c];
        s2 += part[b * 128 + CH + c];
    }
    const float inv_n = 1.0f / (float)NVOX;
    const float mean  = s * inv_n;
    const float var   = s2 * inv_n - mean * mean;
    const float sc    = gamma[c] * rsqrtf(var + EPSV);
    sbuf[c]      = sc;
    sbuf[CH + c] = beta[c] - mean * sc;
}

__global__ void bnrelu_split_kernel(const float* __restrict__ hin,
                                    const float* __restrict__ sbuf,
                                    __nv_bfloat16* __restrict__ ahi,
                                    __nv_bfloat16* __restrict__ alo)
{
    const int i  = blockIdx.x * blockDim.x + threadIdx.x;
    const int c0 = (i * 4) & 63;
    float4 vv = reinterpret_cast<const float4*>(hin)[i];
    float4 sc = reinterpret_cast<const float4*>(sbuf)[c0 >> 2];
    float4 bs = reinterpret_cast<const float4*>(sbuf + CH)[c0 >> 2];
    float a0 = fmaxf(fmaf(vv.x, sc.x, bs.x), 0.0f);
    float a1 = fmaxf(fmaf(vv.y, sc.y, bs.y), 0.0f);
    float a2 = fmaxf(fmaf(vv.z, sc.z, bs.z), 0.0f);
    float a3 = fmaxf(fmaf(vv.w, sc.w, bs.w), 0.0f);
    __nv_bfloat16 h[4], l[4];
    split1(a0, h[0], l[0]); split1(a1, h[1], l[1]);
    split1(a2, h[2], l[2]); split1(a3, h[3], l[3]);
    reinterpret_cast<uint2*>(ahi)[i] = *reinterpret_cast<uint2*>(h);
    reinterpret_cast<uint2*>(alo)[i] = *reinterpret_cast<uint2*>(l);
}

__global__ void final_kernel(const float* __restrict__ hin,
                             const float* __restrict__ sbuf,
                             const float* __restrict__ x,
                             float* __restrict__ out)
{
    const int i  = blockIdx.x * blockDim.x + threadIdx.x;
    const int c0 = (i * 4) & 63;
    float4 vv = reinterpret_cast<const float4*>(hin)[i];
    float4 xx = reinterpret_cast<const float4*>(x)[i];
    float4 sc = reinterpret_cast<const float4*>(sbuf)[c0 >> 2];
    float4 bs = reinterpret_cast<const float4*>(sbuf + CH)[c0 >> 2];
    float4 o;
    o.x = fmaxf(fmaf(vv.x, sc.x, bs.x) + xx.x, 0.0f);
    o.y = fmaxf(fmaf(vv.y, sc.y, bs.y) + xx.y, 0.0f);
    o.z = fmaxf(fmaf(vv.z, sc.z, bs.z) + xx.z, 0.0f);
    o.w = fmaxf(fmaf(vv.w, sc.w, bs.w) + xx.w, 0.0f);
    reinterpret_cast<float4*>(out)[i] = o;
}

// ================= launch =================
extern "C" void kernel_launch(void* const* d_in, const int* in_sizes, int n_in,
                              void* d_out, int out_size)
{
    const float* x   = (const float*)d_in[0];
    const int*   nbr = (const int*)  d_in[1];
    const float* W1  = (const float*)d_in[2];
    const float* ga1 = (const float*)d_in[3];
    const float* be1 = (const float*)d_in[4];
    const float* W2  = (const float*)d_in[5];
    const float* ga2 = (const float*)d_in[6];
    const float* be2 = (const float*)d_in[7];
    float* out = (float*)d_out;

    void *ph, *pxh, *pxl, *pah, *pal, *pwh, *pwl, *pp, *ps;
    cudaGetSymbolAddress(&ph,  g_h);
    cudaGetSymbolAddress(&pxh, g_xhi);  cudaGetSymbolAddress(&pxl, g_xlo);
    cudaGetSymbolAddress(&pah, g_ahi);  cudaGetSymbolAddress(&pal, g_alo);
    cudaGetSymbolAddress(&pwh, g_wthi); cudaGetSymbolAddress(&pwl, g_wtlo);
    cudaGetSymbolAddress(&pp,  g_part); cudaGetSymbolAddress(&ps,  g_sb);
    float* hbuf = (float*)ph;
    __nv_bfloat16* xhi = (__nv_bfloat16*)pxh;  __nv_bfloat16* xlo = (__nv_bfloat16*)pxl;
    __nv_bfloat16* ahi = (__nv_bfloat16*)pah;  __nv_bfloat16* alo = (__nv_bfloat16*)pal;
    __nv_bfloat16* wth = (__nv_bfloat16*)pwh;  __nv_bfloat16* wtl = (__nv_bfloat16*)pwl;
    float* part = (float*)pp;
    float* sbuf = (float*)ps;

    cudaFuncSetAttribute(conv_mma_kernel,
                         cudaFuncAttributeMaxDynamicSharedMemorySize, SMEM_TOTAL);

    const int ew_grid = (NVOX * CH / 4) / TPB;              // 4096
    const int sw_grid = (2 * KTAP * CH * CH) / TPB;         // 864
    const int cv_grid = NVOX / 128;                         // 512
    const int WOFF    = KTAP * CH * CH;                     // 110592

    split_x_kernel<<<ew_grid, TPB>>>(x, xhi, xlo);
    split_w_kernel<<<sw_grid, TPB>>>(W1, W2, wth, wtl);

    // h1 = conv(x, W1); a1 = relu(bn1(h1)) as bf16 split
    conv_mma_kernel<<<cv_grid, 128, SMEM_TOTAL>>>(xhi, xlo, nbr, wth, wtl, hbuf);
    stats_kernel<<<64, TPB>>>(hbuf, part);
    finalize_kernel<<<1, CH>>>(part, ga1, be1, sbuf);
    bnrelu_split_kernel<<<ew_grid, TPB>>>(hbuf, sbuf, ahi, alo);

    // h2 = conv(a1, W2); out = relu(bn2(h2) + x)
    conv_mma_kernel<<<cv_grid, 128, SMEM_TOTAL>>>(ahi, alo, nbr, wth + WOFF, wtl + WOFF, hbuf);
    stats_kernel<<<64, TPB>>>(hbuf, part);
    finalize_kernel<<<1, CH>>>(part, ga2, be2, sbuf);
    final_kernel<<<ew_grid, TPB>>>(hbuf, sbuf, x, out);
}

// round 9
// speedup vs baseline: 3.7486x; 1.5328x over previous
#include <cuda_runtime.h>
#include <cuda_bf16.h>
#include <stdint.h>

#define NVOX 65536
#define KTAP 27
#define CH   64
#define TPB  256
#define EPSV 1e-5f

// ---- SMEM buffer layout (per pipeline buffer), 144B row pitch ----
#define PITCH   144
#define OFF_AHI 0
#define OFF_ALO 18432              // 128 rows * 144
#define OFF_WHI 36864
#define OFF_WLO 46080              // + 64 rows * 144
#define BUFSZ   55296
#define SMEM_TOTAL (2 * BUFSZ)     // 110592 B

// ---------------- scratch (no allocations allowed) ----------------
__device__ float          g_h[NVOX * CH];                // conv output (fp32)
__device__ __nv_bfloat16  g_xhi[NVOX * CH];
__device__ __nv_bfloat16  g_xlo[NVOX * CH];
__device__ __nv_bfloat16  g_ahi[NVOX * CH];
__device__ __nv_bfloat16  g_alo[NVOX * CH];
__device__ __nv_bfloat16  g_wthi[2 * KTAP * CH * CH];    // W^T hi: [w][k][d][c]
__device__ __nv_bfloat16  g_wtlo[2 * KTAP * CH * CH];    // W^T lo
__device__ float          g_part[512 * 2 * CH];          // per-conv-CTA {sum, sumsq}[64]
__device__ float          g_sb[2 * CH];

// ================= PTX helpers (all base-target legal) =================
__device__ __forceinline__ uint32_t smem_u32(const void* p) {
    uint32_t a;
    asm("{ .reg .u64 t; cvta.to.shared.u64 t, %1; cvt.u32.u64 %0, t; }"
        : "=r"(a) : "l"(p));
    return a;
}
__device__ __forceinline__ void cpa16(uint32_t dst, const void* src, uint32_t srcsz) {
    asm volatile("cp.async.ca.shared.global [%0], [%1], 16, %2;"
                 :: "r"(dst), "l"(src), "r"(srcsz) : "memory");
}
#define CPA_COMMIT() asm volatile("cp.async.commit_group;" ::: "memory")
#define CPA_WAIT1()  asm volatile("cp.async.wait_group 1;" ::: "memory")
#define CPA_WAIT0()  asm volatile("cp.async.wait_group 0;" ::: "memory")

#define LDSM4(r0, r1, r2, r3, addr) \
    asm volatile("ldmatrix.sync.aligned.m8n8.x4.shared.b16 {%0,%1,%2,%3}, [%4];" \
                 : "=r"(r0), "=r"(r1), "=r"(r2), "=r"(r3) : "r"(addr))

#define MMA16816(c, a, b0, b1) \
    asm volatile("mma.sync.aligned.m16n8k16.row.col.f32.bf16.bf16.f32 " \
                 "{%0,%1,%2,%3}, {%4,%5,%6,%7}, {%8,%9}, {%0,%1,%2,%3};" \
                 : "+f"((c)[0]), "+f"((c)[1]), "+f"((c)[2]), "+f"((c)[3]) \
                 : "r"((a)[0]), "r"((a)[1]), "r"((a)[2]), "r"((a)[3]), \
                   "r"(b0), "r"(b1))

// ================= conv via mma.sync bf16 (3-product split) =================
// CTA: 128 threads / 4 warps, one 128-voxel tile, full N=64.
// Warp w owns rows [w*32, w*32+32) = 2 m16 tiles x 8 n8 tiles, fp32 accum in regs.
// Per tap: cp.async-staged gathered A rows (hi/lo, zfill inactive) + W^T[k] (hi/lo),
// double buffered; D += Ahi*Whi + Ahi*Wlo + Alo*Whi.
// Epilogue additionally reduces per-channel {sum, sumsq} of this CTA's tile from
// registers (shfl + smem) and writes deterministic per-block partials -> no
// standalone stats kernel, no 16MB re-read.
__global__ void __launch_bounds__(128)
conv_mma_kernel(const __nv_bfloat16* __restrict__ fhi,
                const __nv_bfloat16* __restrict__ flo,
                const int* __restrict__ nbr,
                const __nv_bfloat16* __restrict__ wthi,
                const __nv_bfloat16* __restrict__ wtlo,
                float* __restrict__ out,
                float* __restrict__ part)
{
    extern __shared__ char smem[];
    const uint32_t sbase = smem_u32(smem);
    const int tid  = threadIdx.x;
    const int wid  = tid >> 5, lane = tid & 31;
    const int v0   = blockIdx.x * 128;
    const int rsub = tid >> 3;            // 0..15
    const int chnk = tid & 7;             // 0..7 (16B chunk within 128B row)

    // ---- stage tap k into buffer b (cp.async, zero-fill inactive taps) ----
    auto stage = [&](int b, int k) {
        const uint32_t base = sbase + (uint32_t)b * BUFSZ;
        // A: 128 rows x 128B, hi + lo
#pragma unroll
        for (int i = 0; i < 8; ++i) {
            const int row = rsub + i * 16;
            const int idx = nbr[(v0 + row) * KTAP + k];
            const uint32_t sz = (idx >= 0) ? 16u : 0u;
            const int ic = (idx >= 0) ? idx : 0;
            const char* sh = (const char*)fhi + (size_t)ic * 128 + chnk * 16;
            const char* sl = (const char*)flo + (size_t)ic * 128 + chnk * 16;
            const uint32_t d = base + OFF_AHI + (uint32_t)(row * PITCH + chnk * 16);
            cpa16(d, sh, sz);
            cpa16(d + (OFF_ALO - OFF_AHI), sl, sz);
        }
        // W^T[k]: 64 rows x 128B, hi + lo
        const char* whs = (const char*)wthi + (size_t)k * 8192;
        const char* wls = (const char*)wtlo + (size_t)k * 8192;
#pragma unroll
        for (int i = 0; i < 4; ++i) {
            const int row = rsub + i * 16;            // 0..63
            const uint32_t d = base + OFF_WHI + (uint32_t)(row * PITCH + chnk * 16);
            cpa16(d, whs + row * 128 + chnk * 16, 16);
            cpa16(d + (OFF_WLO - OFF_WHI), wls + row * 128 + chnk * 16, 16);
        }
    };

    float acc[2][8][4];
#pragma unroll
    for (int mt = 0; mt < 2; ++mt)
#pragma unroll
        for (int nt = 0; nt < 8; ++nt)
#pragma unroll
            for (int r = 0; r < 4; ++r) acc[mt][nt][r] = 0.0f;

    // ldmatrix lane->address offsets
    const uint32_t a_loff = (uint32_t)((wid * 32 + (lane & 15)) * PITCH + (lane >> 4) * 16);
    const int g = lane >> 3;
    const uint32_t b_loff = (uint32_t)((((g >> 1) * 8) + (lane & 7)) * PITCH + (g & 1) * 16);

    stage(0, 0);
    CPA_COMMIT();

    for (int k = 0; k < KTAP; ++k) {
        const int b = k & 1;
        if (k + 1 < KTAP) { stage(b ^ 1, k + 1); CPA_COMMIT(); CPA_WAIT1(); }
        else              { CPA_WAIT0(); }
        __syncthreads();                       // tap k staged & visible

        const uint32_t base = sbase + (uint32_t)b * BUFSZ;
#pragma unroll
        for (int ks = 0; ks < 4; ++ks) {
            uint32_t ah[2][4], al[2][4];
#pragma unroll
            for (int mt = 0; mt < 2; ++mt) {
                const uint32_t aaddr = base + OFF_AHI + a_loff
                                     + (uint32_t)(mt * 16 * PITCH + ks * 32);
                LDSM4(ah[mt][0], ah[mt][1], ah[mt][2], ah[mt][3], aaddr);
                LDSM4(al[mt][0], al[mt][1], al[mt][2], al[mt][3],
                      aaddr + (OFF_ALO - OFF_AHI));
            }
#pragma unroll
            for (int nt2 = 0; nt2 < 4; ++nt2) {
                const uint32_t baddr = base + OFF_WHI + b_loff
                                     + (uint32_t)(nt2 * 16 * PITCH + ks * 32);
                uint32_t bh[4], bl[4];
                LDSM4(bh[0], bh[1], bh[2], bh[3], baddr);
                LDSM4(bl[0], bl[1], bl[2], bl[3], baddr + (OFF_WLO - OFF_WHI));
#pragma unroll
                for (int mt = 0; mt < 2; ++mt) {
                    MMA16816(acc[mt][nt2 * 2 + 0], ah[mt], bh[0], bh[1]);
                    MMA16816(acc[mt][nt2 * 2 + 1], ah[mt], bh[2], bh[3]);
                    MMA16816(acc[mt][nt2 * 2 + 0], ah[mt], bl[0], bl[1]);
                    MMA16816(acc[mt][nt2 * 2 + 1], ah[mt], bl[2], bl[3]);
                    MMA16816(acc[mt][nt2 * 2 + 0], al[mt], bh[0], bh[1]);
                    MMA16816(acc[mt][nt2 * 2 + 1], al[mt], bh[2], bh[3]);
                }
            }
        }
        __syncthreads();                       // all warps done with buf b
    }

    // ---- epilogue 1: store result tile ----
    // c-frag m16n8: lane rows (lane>>2), +8; cols (lane&3)*2, +1
    const int r0 = v0 + wid * 32 + (lane >> 2);
    const int c0 = (lane & 3) * 2;
#pragma unroll
    for (int mt = 0; mt < 2; ++mt)
#pragma unroll
        for (int nt = 0; nt < 8; ++nt) {
            float* p0 = out + (size_t)(r0 + mt * 16) * CH + nt * 8 + c0;
            float* p1 = p0 + 8 * CH;
            *reinterpret_cast<float2*>(p0) = make_float2(acc[mt][nt][0], acc[mt][nt][1]);
            *reinterpret_cast<float2*>(p1) = make_float2(acc[mt][nt][2], acc[mt][nt][3]);
        }

    // ---- epilogue 2: fused BN stats (per-channel sum & sumsq of this tile) ----
    // Per thread: 16 channels (nt x j). Reduce the 8 row-lanes (lane>>2) via shfl.
    float s[8][2], q[8][2];
#pragma unroll
    for (int nt = 0; nt < 8; ++nt)
#pragma unroll
        for (int j = 0; j < 2; ++j) {
            float a0 = acc[0][nt][j],     a1 = acc[0][nt][j + 2];
            float a2 = acc[1][nt][j],     a3 = acc[1][nt][j + 2];
            s[nt][j] = (a0 + a1) + (a2 + a3);
            q[nt][j] = (a0 * a0 + a1 * a1) + (a2 * a2 + a3 * a3);
        }
#pragma unroll
    for (int st = 4; st < 32; st <<= 1)
#pragma unroll
        for (int nt = 0; nt < 8; ++nt)
#pragma unroll
            for (int j = 0; j < 2; ++j) {
                s[nt][j] += __shfl_xor_sync(0xFFFFFFFFu, s[nt][j], st);
                q[nt][j] += __shfl_xor_sync(0xFFFFFFFFu, q[nt][j], st);
            }
    // lanes 0..3 now hold warp totals for channels nt*8 + 2*lane + j.
    // Reuse (now dead) pipeline smem: red[w][p][c], 4*2*64 floats = 2KB.
    float* red = reinterpret_cast<float*>(smem);
    if (lane < 4) {
#pragma unroll
        for (int nt = 0; nt < 8; ++nt)
#pragma unroll
            for (int j = 0; j < 2; ++j) {
                const int c = nt * 8 + 2 * lane + j;
                red[(wid * 2 + 0) * CH + c] = s[nt][j];
                red[(wid * 2 + 1) * CH + c] = q[nt][j];
            }
    }
    __syncthreads();
    if (tid < CH) {
        float ts = 0.0f, tq = 0.0f;
#pragma unroll
        for (int w = 0; w < 4; ++w) {
            ts += red[(w * 2 + 0) * CH + tid];
            tq += red[(w * 2 + 1) * CH + tid];
        }
        part[blockIdx.x * 128 + tid]      = ts;
        part[blockIdx.x * 128 + CH + tid] = tq;
    }
}

// ================= prep / BN / elementwise kernels =================
__device__ __forceinline__ void split1(float v, __nv_bfloat16& h, __nv_bfloat16& l) {
    h = __float2bfloat16_rn(v);
    l = __float2bfloat16_rn(v - __bfloat162float(h));
}

__global__ void split_x_kernel(const float* __restrict__ x,
                               __nv_bfloat16* __restrict__ xhi,
                               __nv_bfloat16* __restrict__ xlo)
{
    const int i = blockIdx.x * blockDim.x + threadIdx.x;
    float4 v = reinterpret_cast<const float4*>(x)[i];
    __nv_bfloat16 h[4], l[4];
    split1(v.x, h[0], l[0]); split1(v.y, h[1], l[1]);
    split1(v.z, h[2], l[2]); split1(v.w, h[3], l[3]);
    reinterpret_cast<uint2*>(xhi)[i] = *reinterpret_cast<uint2*>(h);
    reinterpret_cast<uint2*>(xlo)[i] = *reinterpret_cast<uint2*>(l);
}

// Wt[w][k][d][c] = split(W_w[k][c][d])  (c contiguous -> [n][k] rows for ldmatrix)
__global__ void split_w_kernel(const float* __restrict__ W1,
                               const float* __restrict__ W2,
                               __nv_bfloat16* __restrict__ wthi,
                               __nv_bfloat16* __restrict__ wtlo)
{
    const int t = blockIdx.x * blockDim.x + threadIdx.x;
    const int widx = t / (KTAP * CH * CH);
    const int rem  = t % (KTAP * CH * CH);
    const int k = rem / (CH * CH);
    const int d = (rem % (CH * CH)) / CH;
    const int c = rem % CH;
    const float* W = widx ? W2 : W1;
    __nv_bfloat16 h, l;
    split1(W[k * CH * CH + c * CH + d], h, l);
    wthi[t] = h; wtlo[t] = l;
}

// sum 512 per-block partials -> folded BN affine {scale, bias}
__global__ void finalize_kernel(const float* __restrict__ part,
                                const float* __restrict__ gamma,
                                const float* __restrict__ beta,
                                float* __restrict__ sbuf)
{
    __shared__ float sm[4][2][CH];
    const int t = threadIdx.x, c = t & 63, grp = t >> 6;   // 256 threads
    float s = 0.0f, q = 0.0f;
    for (int b = grp; b < 512; b += 4) {
        s += part[b * 128 + c];
        q += part[b * 128 + CH + c];
    }
    sm[grp][0][c] = s; sm[grp][1][c] = q;
    __syncthreads();
    if (t < CH) {
        float ts = sm[0][0][t] + sm[1][0][t] + sm[2][0][t] + sm[3][0][t];
        float tq = sm[0][1][t] + sm[1][1][t] + sm[2][1][t] + sm[3][1][t];
        const float inv_n = 1.0f / (float)NVOX;
        const float mean  = ts * inv_n;
        const float var   = tq * inv_n - mean * mean;
        const float sc    = gamma[t] * rsqrtf(var + EPSV);
        sbuf[t]      = sc;
        sbuf[CH + t] = beta[t] - mean * sc;
    }
}

__global__ void bnrelu_split_kernel(const float* __restrict__ hin,
                                    const float* __restrict__ sbuf,
                                    __nv_bfloat16* __restrict__ ahi,
                                    __nv_bfloat16* __restrict__ alo)
{
    const int i  = blockIdx.x * blockDim.x + threadIdx.x;
    const int c0 = (i * 4) & 63;
    float4 vv = reinterpret_cast<const float4*>(hin)[i];
    float4 sc = reinterpret_cast<const float4*>(sbuf)[c0 >> 2];
    float4 bs = reinterpret_cast<const float4*>(sbuf + CH)[c0 >> 2];
    float a0 = fmaxf(fmaf(vv.x, sc.x, bs.x), 0.0f);
    float a1 = fmaxf(fmaf(vv.y, sc.y, bs.y), 0.0f);
    float a2 = fmaxf(fmaf(vv.z, sc.z, bs.z), 0.0f);
    float a3 = fmaxf(fmaf(vv.w, sc.w, bs.w), 0.0f);
    __nv_bfloat16 h[4], l[4];
    split1(a0, h[0], l[0]); split1(a1, h[1], l[1]);
    split1(a2, h[2], l[2]); split1(a3, h[3], l[3]);
    reinterpret_cast<uint2*>(ahi)[i] = *reinterpret_cast<uint2*>(h);
    reinterpret_cast<uint2*>(alo)[i] = *reinterpret_cast<uint2*>(l);
}

__global__ void final_kernel(const float* __restrict__ hin,
                             const float* __restrict__ sbuf,
                             const float* __restrict__ x,
                             float* __restrict__ out)
{
    const int i  = blockIdx.x * blockDim.x + threadIdx.x;
    const int c0 = (i * 4) & 63;
    float4 vv = reinterpret_cast<const float4*>(hin)[i];
    float4 xx = reinterpret_cast<const float4*>(x)[i];
    float4 sc = reinterpret_cast<const float4*>(sbuf)[c0 >> 2];
    float4 bs = reinterpret_cast<const float4*>(sbuf + CH)[c0 >> 2];
    float4 o;
    o.x = fmaxf(fmaf(vv.x, sc.x, bs.x) + xx.x, 0.0f);
    o.y = fmaxf(fmaf(vv.y, sc.y, bs.y) + xx.y, 0.0f);
    o.z = fmaxf(fmaf(vv.z, sc.z, bs.z) + xx.z, 0.0f);
    o.w = fmaxf(fmaf(vv.w, sc.w, bs.w) + xx.w, 0.0f);
    reinterpret_cast<float4*>(out)[i] = o;
}

// ================= launch =================
extern "C" void kernel_launch(void* const* d_in, const int* in_sizes, int n_in,
                              void* d_out, int out_size)
{
    const float* x   = (const float*)d_in[0];
    const int*   nbr = (const int*)  d_in[1];
    const float* W1  = (const float*)d_in[2];
    const float* ga1 = (const float*)d_in[3];
    const float* be1 = (const float*)d_in[4];
    const float* W2  = (const float*)d_in[5];
    const float* ga2 = (const float*)d_in[6];
    const float* be2 = (const float*)d_in[7];
    float* out = (float*)d_out;

    void *ph, *pxh, *pxl, *pah, *pal, *pwh, *pwl, *pp, *ps;
    cudaGetSymbolAddress(&ph,  g_h);
    cudaGetSymbolAddress(&pxh, g_xhi);  cudaGetSymbolAddress(&pxl, g_xlo);
    cudaGetSymbolAddress(&pah, g_ahi);  cudaGetSymbolAddress(&pal, g_alo);
    cudaGetSymbolAddress(&pwh, g_wthi); cudaGetSymbolAddress(&pwl, g_wtlo);
    cudaGetSymbolAddress(&pp,  g_part); cudaGetSymbolAddress(&ps,  g_sb);
    float* hbuf = (float*)ph;
    __nv_bfloat16* xhi = (__nv_bfloat16*)pxh;  __nv_bfloat16* xlo = (__nv_bfloat16*)pxl;
    __nv_bfloat16* ahi = (__nv_bfloat16*)pah;  __nv_bfloat16* alo = (__nv_bfloat16*)pal;
    __nv_bfloat16* wth = (__nv_bfloat16*)pwh;  __nv_bfloat16* wtl = (__nv_bfloat16*)pwl;
    float* part = (float*)pp;
    float* sbuf = (float*)ps;

    cudaFuncSetAttribute(conv_mma_kernel,
                         cudaFuncAttributeMaxDynamicSharedMemorySize, SMEM_TOTAL);

    const int ew_grid = (NVOX * CH / 4) / TPB;              // 4096
    const int sw_grid = (2 * KTAP * CH * CH) / TPB;         // 864
    const int cv_grid = NVOX / 128;                         // 512
    const int WOFF    = KTAP * CH * CH;                     // 110592

    split_x_kernel<<<ew_grid, TPB>>>(x, xhi, xlo);
    split_w_kernel<<<sw_grid, TPB>>>(W1, W2, wth, wtl);

    // h1 = conv(x, W1) with fused stats; a1 = relu(bn1(h1)) as bf16 split
    conv_mma_kernel<<<cv_grid, 128, SMEM_TOTAL>>>(xhi, xlo, nbr, wth, wtl, hbuf, part);
    finalize_kernel<<<1, TPB>>>(part, ga1, be1, sbuf);
    bnrelu_split_kernel<<<ew_grid, TPB>>>(hbuf, sbuf, ahi, alo);

    // h2 = conv(a1, W2) with fused stats; out = relu(bn2(h2) + x)
    conv_mma_kernel<<<cv_grid, 128, SMEM_TOTAL>>>(ahi, alo, nbr, wth + WOFF, wtl + WOFF, hbuf, part);
    finalize_kernel<<<1, TPB>>>(part, ga2, be2, sbuf);
    final_kernel<<<ew_grid, TPB>>>(hbuf, sbuf, x, out);
}

// round 10
// speedup vs baseline: 4.0711x; 1.0860x over previous
#include <cuda_runtime.h>
#include <cuda_bf16.h>
#include <stdint.h>

#define NVOX 65536
#define KTAP 27
#define CH   64
#define TPB  256
#define EPSV 1e-5f

// ---- SMEM buffer layout (per pipeline buffer), SW128-swizzled 128B rows ----
#define OFF_AHI 0
#define OFF_ALO 16384              // 128 rows * 128
#define OFF_WHI 32768
#define OFF_WLO 40960              // + 64 rows * 128
#define BUFSZ   49152
#define SMEM_TOTAL (2 * BUFSZ)     // 98304 B -> 2 CTAs/SM

// ---------------- scratch (no allocations allowed) ----------------
__device__ float          g_h[NVOX * CH];                // conv output (fp32)
__device__ __nv_bfloat16  g_xhi[NVOX * CH];
__device__ __nv_bfloat16  g_xlo[NVOX * CH];
__device__ __nv_bfloat16  g_ahi[NVOX * CH];
__device__ __nv_bfloat16  g_alo[NVOX * CH];
__device__ __nv_bfloat16  g_wthi[2 * KTAP * CH * CH];    // W^T hi: [w][k][d][c]
__device__ __nv_bfloat16  g_wtlo[2 * KTAP * CH * CH];    // W^T lo
__device__ float          g_part[512 * 2 * CH];          // per-conv-CTA {sum, sumsq}[64]
__device__ float          g_sb[2 * CH];

// ================= PTX helpers (all base-target legal) =================
__device__ __forceinline__ uint32_t smem_u32(const void* p) {
    uint32_t a;
    asm("{ .reg .u64 t; cvta.to.shared.u64 t, %1; cvt.u32.u64 %0, t; }"
        : "=r"(a) : "l"(p));
    return a;
}
__device__ __forceinline__ void cpa16(uint32_t dst, const void* src, uint32_t srcsz) {
    asm volatile("cp.async.ca.shared.global [%0], [%1], 16, %2;"
                 :: "r"(dst), "l"(src), "r"(srcsz) : "memory");
}
#define CPA_COMMIT() asm volatile("cp.async.commit_group;" ::: "memory")
#define CPA_WAIT1()  asm volatile("cp.async.wait_group 1;" ::: "memory")
#define CPA_WAIT0()  asm volatile("cp.async.wait_group 0;" ::: "memory")

#define LDSM4(r0, r1, r2, r3, addr) \
    asm volatile("ldmatrix.sync.aligned.m8n8.x4.shared.b16 {%0,%1,%2,%3}, [%4];" \
                 : "=r"(r0), "=r"(r1), "=r"(r2), "=r"(r3) : "r"(addr))

#define MMA16816(c, a, b0, b1) \
    asm volatile("mma.sync.aligned.m16n8k16.row.col.f32.bf16.bf16.f32 " \
                 "{%0,%1,%2,%3}, {%4,%5,%6,%7}, {%8,%9}, {%0,%1,%2,%3};" \
                 : "+f"((c)[0]), "+f"((c)[1]), "+f"((c)[2]), "+f"((c)[3]) \
                 : "r"((a)[0]), "r"((a)[1]), "r"((a)[2]), "r"((a)[3]), \
                   "r"(b0), "r"(b1))

// ================= conv via mma.sync bf16 (3-product split) =================
// CTA: 128 threads / 4 warps, one 128-voxel tile, full N=64; 2 CTAs/SM.
// SW128 swizzle: element (row, col) lives at row*128 + (col ^ ((row&7)<<4))
// (granule-level XOR; row&7 == lane&7 for every fragment row this thread touches,
// so the XOR term is a per-thread constant).
// Per tap: cp.async-staged gathered A rows (hi/lo, zfill inactive) + W^T[k] (hi/lo),
// double buffered; D += Ahi*Whi + Ahi*Wlo + Alo*Whi. Epilogue fuses BN stats.
__global__ void __launch_bounds__(128, 2)
conv_mma_kernel(const __nv_bfloat16* __restrict__ fhi,
                const __nv_bfloat16* __restrict__ flo,
                const int* __restrict__ nbr,
                const __nv_bfloat16* __restrict__ wthi,
                const __nv_bfloat16* __restrict__ wtlo,
                float* __restrict__ out,
                float* __restrict__ part)
{
    extern __shared__ char smem[];
    const uint32_t sbase = smem_u32(smem);
    const int tid  = threadIdx.x;
    const int wid  = tid >> 5, lane = tid & 31;
    const int v0   = blockIdx.x * 128;
    const int rsub = tid >> 3;            // 0..15  (staging row subgroup)
    const int chnk = tid & 7;             // 0..7   (16B chunk within 128B row)
    const uint32_t st_csw = (uint32_t)((chnk * 16) ^ ((rsub & 7) << 4)); // staging col'

    // ---- stage tap k into buffer b (cp.async, zero-fill inactive taps) ----
    auto stage = [&](int b, int k) {
        const uint32_t base = sbase + (uint32_t)b * BUFSZ;
        // A: 128 rows x 128B, hi + lo
#pragma unroll
        for (int i = 0; i < 8; ++i) {
            const int row = rsub + i * 16;
            const int idx = nbr[(v0 + row) * KTAP + k];
            const uint32_t sz = (idx >= 0) ? 16u : 0u;
            const int ic = (idx >= 0) ? idx : 0;
            const char* sh = (const char*)fhi + (size_t)ic * 128 + chnk * 16;
            const char* sl = (const char*)flo + (size_t)ic * 128 + chnk * 16;
            const uint32_t d = base + OFF_AHI + (uint32_t)(row * 128) + st_csw;
            cpa16(d, sh, sz);
            cpa16(d + (OFF_ALO - OFF_AHI), sl, sz);
        }
        // W^T[k]: 64 rows x 128B, hi + lo
        const char* whs = (const char*)wthi + (size_t)k * 8192;
        const char* wls = (const char*)wtlo + (size_t)k * 8192;
#pragma unroll
        for (int i = 0; i < 4; ++i) {
            const int row = rsub + i * 16;            // 0..63
            const uint32_t d = base + OFF_WHI + (uint32_t)(row * 128) + st_csw;
            cpa16(d, whs + row * 128 + chnk * 16, 16);
            cpa16(d + (OFF_WLO - OFF_WHI), wls + row * 128 + chnk * 16, 16);
        }
    };

    float acc[2][8][4];
#pragma unroll
    for (int mt = 0; mt < 2; ++mt)
#pragma unroll
        for (int nt = 0; nt < 8; ++nt)
#pragma unroll
            for (int r = 0; r < 4; ++r) acc[mt][nt][r] = 0.0f;

    // ldmatrix lane->address pieces (swizzled)
    const uint32_t lxor   = (uint32_t)((lane & 7) << 4);               // (row&7)<<4
    const uint32_t a_rowb = (uint32_t)((wid * 32 + (lane & 15)) * 128);
    const uint32_t a_colb = (uint32_t)((lane >> 4) * 16);
    const int g = lane >> 3;
    const uint32_t b_rowb = (uint32_t)((((g >> 1) * 8) + (lane & 7)) * 128);
    const uint32_t b_colb = (uint32_t)((g & 1) * 16);

    stage(0, 0);
    CPA_COMMIT();

    for (int k = 0; k < KTAP; ++k) {
        const int b = k & 1;
        if (k + 1 < KTAP) { stage(b ^ 1, k + 1); CPA_COMMIT(); CPA_WAIT1(); }
        else              { CPA_WAIT0(); }
        __syncthreads();                       // tap k staged & visible

        const uint32_t base = sbase + (uint32_t)b * BUFSZ;
#pragma unroll
        for (int ks = 0; ks < 4; ++ks) {
            const uint32_t a_csw = (uint32_t)(ks * 32 + a_colb) ^ lxor;
            const uint32_t b_csw = (uint32_t)(ks * 32 + b_colb) ^ lxor;
            uint32_t ah[2][4], al[2][4];
#pragma unroll
            for (int mt = 0; mt < 2; ++mt) {
                const uint32_t aaddr = base + OFF_AHI + a_rowb
                                     + (uint32_t)(mt * 2048) + a_csw;
                LDSM4(ah[mt][0], ah[mt][1], ah[mt][2], ah[mt][3], aaddr);
                LDSM4(al[mt][0], al[mt][1], al[mt][2], al[mt][3],
                      aaddr + (OFF_ALO - OFF_AHI));
            }
#pragma unroll
            for (int nt2 = 0; nt2 < 4; ++nt2) {
                const uint32_t baddr = base + OFF_WHI + b_rowb
                                     + (uint32_t)(nt2 * 2048) + b_csw;
                uint32_t bh[4], bl[4];
                LDSM4(bh[0], bh[1], bh[2], bh[3], baddr);
                LDSM4(bl[0], bl[1], bl[2], bl[3], baddr + (OFF_WLO - OFF_WHI));
#pragma unroll
                for (int mt = 0; mt < 2; ++mt) {
                    MMA16816(acc[mt][nt2 * 2 + 0], ah[mt], bh[0], bh[1]);
                    MMA16816(acc[mt][nt2 * 2 + 1], ah[mt], bh[2], bh[3]);
                    MMA16816(acc[mt][nt2 * 2 + 0], ah[mt], bl[0], bl[1]);
                    MMA16816(acc[mt][nt2 * 2 + 1], ah[mt], bl[2], bl[3]);
                    MMA16816(acc[mt][nt2 * 2 + 0], al[mt], bh[0], bh[1]);
                    MMA16816(acc[mt][nt2 * 2 + 1], al[mt], bh[2], bh[3]);
                }
            }
        }
        __syncthreads();                       // all warps done with buf b
    }

    // ---- epilogue 1: store result tile ----
    const int r0 = v0 + wid * 32 + (lane >> 2);
    const int c0 = (lane & 3) * 2;
#pragma unroll
    for (int mt = 0; mt < 2; ++mt)
#pragma unroll
        for (int nt = 0; nt < 8; ++nt) {
            float* p0 = out + (size_t)(r0 + mt * 16) * CH + nt * 8 + c0;
            float* p1 = p0 + 8 * CH;
            *reinterpret_cast<float2*>(p0) = make_float2(acc[mt][nt][0], acc[mt][nt][1]);
            *reinterpret_cast<float2*>(p1) = make_float2(acc[mt][nt][2], acc[mt][nt][3]);
        }

    // ---- epilogue 2: fused BN stats (per-channel sum & sumsq of this tile) ----
    float s[8][2], q[8][2];
#pragma unroll
    for (int nt = 0; nt < 8; ++nt)
#pragma unroll
        for (int j = 0; j < 2; ++j) {
            float a0 = acc[0][nt][j],     a1 = acc[0][nt][j + 2];
            float a2 = acc[1][nt][j],     a3 = acc[1][nt][j + 2];
            s[nt][j] = (a0 + a1) + (a2 + a3);
            q[nt][j] = (a0 * a0 + a1 * a1) + (a2 * a2 + a3 * a3);
        }
#pragma unroll
    for (int st = 4; st < 32; st <<= 1)
#pragma unroll
        for (int nt = 0; nt < 8; ++nt)
#pragma unroll
            for (int j = 0; j < 2; ++j) {
                s[nt][j] += __shfl_xor_sync(0xFFFFFFFFu, s[nt][j], st);
                q[nt][j] += __shfl_xor_sync(0xFFFFFFFFu, q[nt][j], st);
            }
    float* red = reinterpret_cast<float*>(smem);     // 2KB, pipeline bufs dead
    if (lane < 4) {
#pragma unroll
        for (int nt = 0; nt < 8; ++nt)
#pragma unroll
            for (int j = 0; j < 2; ++j) {
                const int c = nt * 8 + 2 * lane + j;
                red[(wid * 2 + 0) * CH + c] = s[nt][j];
                red[(wid * 2 + 1) * CH + c] = q[nt][j];
            }
    }
    __syncthreads();
    if (tid < CH) {
        float ts = 0.0f, tq = 0.0f;
#pragma unroll
        for (int w = 0; w < 4; ++w) {
            ts += red[(w * 2 + 0) * CH + tid];
            tq += red[(w * 2 + 1) * CH + tid];
        }
        part[blockIdx.x * 128 + tid]      = ts;
        part[blockIdx.x * 128 + CH + tid] = tq;
    }
}

// ================= prep / BN / elementwise kernels =================
__device__ __forceinline__ void split1(float v, __nv_bfloat16& h, __nv_bfloat16& l) {
    h = __float2bfloat16_rn(v);
    l = __float2bfloat16_rn(v - __bfloat162float(h));
}

__global__ void split_x_kernel(const float* __restrict__ x,
                               __nv_bfloat16* __restrict__ xhi,
                               __nv_bfloat16* __restrict__ xlo)
{
    const int i = blockIdx.x * blockDim.x + threadIdx.x;
    float4 v = reinterpret_cast<const float4*>(x)[i];
    __nv_bfloat16 h[4], l[4];
    split1(v.x, h[0], l[0]); split1(v.y, h[1], l[1]);
    split1(v.z, h[2], l[2]); split1(v.w, h[3], l[3]);
    reinterpret_cast<uint2*>(xhi)[i] = *reinterpret_cast<uint2*>(h);
    reinterpret_cast<uint2*>(xlo)[i] = *reinterpret_cast<uint2*>(l);
}

// Wt[w][k][d][c] = split(W_w[k][c][d])
__global__ void split_w_kernel(const float* __restrict__ W1,
                               const float* __restrict__ W2,
                               __nv_bfloat16* __restrict__ wthi,
                               __nv_bfloat16* __restrict__ wtlo)
{
    const int t = blockIdx.x * blockDim.x + threadIdx.x;
    const int widx = t / (KTAP * CH * CH);
    const int rem  = t % (KTAP * CH * CH);
    const int k = rem / (CH * CH);
    const int d = (rem % (CH * CH)) / CH;
    const int c = rem % CH;
    const float* W = widx ? W2 : W1;
    __nv_bfloat16 h, l;
    split1(W[k * CH * CH + c * CH + d], h, l);
    wthi[t] = h; wtlo[t] = l;
}

// sum 512 per-block partials -> folded BN affine {scale, bias}
// Parallel/coalesced: thread t reduces float4-column (t&31) over rows t>>5 + 8n.
__global__ void finalize_kernel(const float* __restrict__ part,
                                const float* __restrict__ gamma,
                                const float* __restrict__ beta,
                                float* __restrict__ sbuf)
{
    __shared__ float4 sm[8][32];
    const int t  = threadIdx.x;           // 256
    const int c4 = t & 31;                // float4 col within 128-float row
    const int gp = t >> 5;                // 8 row groups
    const float4* p4 = reinterpret_cast<const float4*>(part);
    float4 a = make_float4(0.f, 0.f, 0.f, 0.f);
#pragma unroll 4
    for (int b = gp; b < 512; b += 8) {
        float4 v = p4[b * 32 + c4];
        a.x += v.x; a.y += v.y; a.z += v.z; a.w += v.w;
    }
    sm[gp][c4] = a;
    __syncthreads();
    __shared__ float4 tot[32];
    if (t < 32) {
        float4 r = make_float4(0.f, 0.f, 0.f, 0.f);
#pragma unroll
        for (int gg = 0; gg < 8; ++gg) {
            float4 v = sm[gg][t];
            r.x += v.x; r.y += v.y; r.z += v.z; r.w += v.w;
        }
        tot[t] = r;
    }
    __syncthreads();
    if (t < 16) {                         // cols 0-15 = sums, 16-31 = sumsq
        float4 s = tot[t], q = tot[t + 16];
        const float inv_n = 1.0f / (float)NVOX;
        const float sv[4] = {s.x, s.y, s.z, s.w};
        const float qv[4] = {q.x, q.y, q.z, q.w};
#pragma unroll
        for (int e = 0; e < 4; ++e) {
            const int ch = t * 4 + e;
            const float mean = sv[e] * inv_n;
            const float var  = qv[e] * inv_n - mean * mean;
            const float sc   = gamma[ch] * rsqrtf(var + EPSV);
            sbuf[ch]      = sc;
            sbuf[CH + ch] = beta[ch] - mean * sc;
        }
    }
}

__global__ void bnrelu_split_kernel(const float* __restrict__ hin,
                                    const float* __restrict__ sbuf,
                                    __nv_bfloat16* __restrict__ ahi,
                                    __nv_bfloat16* __restrict__ alo)
{
    const int i  = blockIdx.x * blockDim.x + threadIdx.x;
    const int c0 = (i * 4) & 63;
    float4 vv = reinterpret_cast<const float4*>(hin)[i];
    float4 sc = reinterpret_cast<const float4*>(sbuf)[c0 >> 2];
    float4 bs = reinterpret_cast<const float4*>(sbuf + CH)[c0 >> 2];
    float a0 = fmaxf(fmaf(vv.x, sc.x, bs.x), 0.0f);
    float a1 = fmaxf(fmaf(vv.y, sc.y, bs.y), 0.0f);
    float a2 = fmaxf(fmaf(vv.z, sc.z, bs.z), 0.0f);
    float a3 = fmaxf(fmaf(vv.w, sc.w, bs.w), 0.0f);
    __nv_bfloat16 h[4], l[4];
    split1(a0, h[0], l[0]); split1(a1, h[1], l[1]);
    split1(a2, h[2], l[2]); split1(a3, h[3], l[3]);
    reinterpret_cast<uint2*>(ahi)[i] = *reinterpret_cast<uint2*>(h);
    reinterpret_cast<uint2*>(alo)[i] = *reinterpret_cast<uint2*>(l);
}

__global__ void final_kernel(const float* __restrict__ hin,
                             const float* __restrict__ sbuf,
                             const float* __restrict__ x,
                             float* __restrict__ out)
{
    const int i  = blockIdx.x * blockDim.x + threadIdx.x;
    const int c0 = (i * 4) & 63;
    float4 vv = reinterpret_cast<const float4*>(hin)[i];
    float4 xx = reinterpret_cast<const float4*>(x)[i];
    float4 sc = reinterpret_cast<const float4*>(sbuf)[c0 >> 2];
    float4 bs = reinterpret_cast<const float4*>(sbuf + CH)[c0 >> 2];
    float4 o;
    o.x = fmaxf(fmaf(vv.x, sc.x, bs.x) + xx.x, 0.0f);
    o.y = fmaxf(fmaf(vv.y, sc.y, bs.y) + xx.y, 0.0f);
    o.z = fmaxf(fmaf(vv.z, sc.z, bs.z) + xx.z, 0.0f);
    o.w = fmaxf(fmaf(vv.w, sc.w, bs.w) + xx.w, 0.0f);
    reinterpret_cast<float4*>(out)[i] = o;
}

// ================= launch =================
extern "C" void kernel_launch(void* const* d_in, const int* in_sizes, int n_in,
                              void* d_out, int out_size)
{
    const float* x   = (const float*)d_in[0];
    const int*   nbr = (const int*)  d_in[1];
    const float* W1  = (const float*)d_in[2];
    const float* ga1 = (const float*)d_in[3];
    const float* be1 = (const float*)d_in[4];
    const float* W2  = (const float*)d_in[5];
    const float* ga2 = (const float*)d_in[6];
    const float* be2 = (const float*)d_in[7];
    float* out = (float*)d_out;

    void *ph, *pxh, *pxl, *pah, *pal, *pwh, *pwl, *pp, *ps;
    cudaGetSymbolAddress(&ph,  g_h);
    cudaGetSymbolAddress(&pxh, g_xhi);  cudaGetSymbolAddress(&pxl, g_xlo);
    cudaGetSymbolAddress(&pah, g_ahi);  cudaGetSymbolAddress(&pal, g_alo);
    cudaGetSymbolAddress(&pwh, g_wthi); cudaGetSymbolAddress(&pwl, g_wtlo);
    cudaGetSymbolAddress(&pp,  g_part); cudaGetSymbolAddress(&ps,  g_sb);
    float* hbuf = (float*)ph;
    __nv_bfloat16* xhi = (__nv_bfloat16*)pxh;  __nv_bfloat16* xlo = (__nv_bfloat16*)pxl;
    __nv_bfloat16* ahi = (__nv_bfloat16*)pah;  __nv_bfloat16* alo = (__nv_bfloat16*)pal;
    __nv_bfloat16* wth = (__nv_bfloat16*)pwh;  __nv_bfloat16* wtl = (__nv_bfloat16*)pwl;
    float* part = (float*)pp;
    float* sbuf = (float*)ps;

    cudaFuncSetAttribute(conv_mma_kernel,
                         cudaFuncAttributeMaxDynamicSharedMemorySize, SMEM_TOTAL);

    const int ew_grid = (NVOX * CH / 4) / TPB;              // 4096
    const int sw_grid = (2 * KTAP * CH * CH) / TPB;         // 864
    const int cv_grid = NVOX / 128;                         // 512
    const int WOFF    = KTAP * CH * CH;                     // 110592

    split_x_kernel<<<ew_grid, TPB>>>(x, xhi, xlo);
    split_w_kernel<<<sw_grid, TPB>>>(W1, W2, wth, wtl);

    // h1 = conv(x, W1) with fused stats; a1 = relu(bn1(h1)) as bf16 split
    conv_mma_kernel<<<cv_grid, 128, SMEM_TOTAL>>>(xhi, xlo, nbr, wth, wtl, hbuf, part);
    finalize_kernel<<<1, TPB>>>(part, ga1, be1, sbuf);
    bnrelu_split_kernel<<<ew_grid, TPB>>>(hbuf, sbuf, ahi, alo);

    // h2 = conv(a1, W2) with fused stats; out = relu(bn2(h2) + x)
    conv_mma_kernel<<<cv_grid, 128, SMEM_TOTAL>>>(ahi, alo, nbr, wth + WOFF, wtl + WOFF, hbuf, part);
    finalize_kernel<<<1, TPB>>>(part, ga2, be2, sbuf);
    final_kernel<<<ew_grid, TPB>>>(hbuf, sbuf, x, out);
}

// round 11
// speedup vs baseline: 6.0529x; 1.4868x over previous
#include <cuda_runtime.h>
#include <cuda_fp16.h>
#include <stdint.h>

#define NVOX 65536
#define KTAP 27
#define CH   64
#define TPB  256
#define EPSV 1e-5f

// ---- SMEM per pipeline buffer: A(fp16) 16KB | Whi 8KB | Wlo 8KB ----
#define OFF_A   0
#define OFF_WHI 16384
#define OFF_WLO 24576
#define BUFSZ   32768
#define SMEM_TOTAL (2 * BUFSZ)     // 65536 B -> 3 CTAs/SM

// ---------------- scratch (no allocations allowed) ----------------
__device__ float   g_h[NVOX * CH];               // conv output (fp32)
__device__ __half  g_xh[NVOX * CH];              // x as fp16
__device__ __half  g_ah[NVOX * CH];              // activations as fp16
__device__ __half  g_wthi[2 * KTAP * CH * CH];   // W^T hi: [w][k][d][c]
__device__ __half  g_wtlo[2 * KTAP * CH * CH];   // W^T lo
__device__ float   g_part[512 * 2 * CH];         // per-conv-CTA {sum, sumsq}[64]
__device__ float   g_part2[8 * 2 * CH];          // stage-1 reduced partials
__device__ float   g_sb[2 * CH];                 // folded BN affine

// ================= PTX helpers =================
__device__ __forceinline__ uint32_t smem_u32(const void* p) {
    uint32_t a;
    asm("{ .reg .u64 t; cvta.to.shared.u64 t, %1; cvt.u32.u64 %0, t; }"
        : "=r"(a) : "l"(p));
    return a;
}
__device__ __forceinline__ void cpa16(uint32_t dst, const void* src, uint32_t srcsz) {
    asm volatile("cp.async.ca.shared.global [%0], [%1], 16, %2;"
                 :: "r"(dst), "l"(src), "r"(srcsz) : "memory");
}
#define CPA_COMMIT() asm volatile("cp.async.commit_group;" ::: "memory")
#define CPA_WAIT1()  asm volatile("cp.async.wait_group 1;" ::: "memory")
#define CPA_WAIT0()  asm volatile("cp.async.wait_group 0;" ::: "memory")

#define LDSM4(r0, r1, r2, r3, addr) \
    asm volatile("ldmatrix.sync.aligned.m8n8.x4.shared.b16 {%0,%1,%2,%3}, [%4];" \
                 : "=r"(r0), "=r"(r1), "=r"(r2), "=r"(r3) : "r"(addr))

#define MMA16816(c, a, b0, b1) \
    asm volatile("mma.sync.aligned.m16n8k16.row.col.f32.f16.f16.f32 " \
                 "{%0,%1,%2,%3}, {%4,%5,%6,%7}, {%8,%9}, {%0,%1,%2,%3};" \
                 : "+f"((c)[0]), "+f"((c)[1]), "+f"((c)[2]), "+f"((c)[3]) \
                 : "r"((a)[0]), "r"((a)[1]), "r"((a)[2]), "r"((a)[3]), \
                   "r"(b0), "r"(b1))

// ================= conv via mma.sync fp16 (2-product W-split) =================
// CTA: 128 threads / 4 warps, one 128-voxel tile, full N=64; 3 CTAs/SM.
// A truncated to fp16 (rel err <= 2^-12); W = Whi + Wlo (fp16 split, ~2^-22).
// D += A*Whi + A*Wlo. SW128 swizzle: (row, col) -> row*128 + (col ^ ((row&7)<<4)).
// Epilogue fuses BN stats into deterministic per-block partials.
__global__ void __launch_bounds__(128, 3)
conv_mma_kernel(const __half* __restrict__ fh,
                const int* __restrict__ nbr,
                const __half* __restrict__ wthi,
                const __half* __restrict__ wtlo,
                float* __restrict__ out,
                float* __restrict__ part)
{
    extern __shared__ char smem[];
    const uint32_t sbase = smem_u32(smem);
    const int tid  = threadIdx.x;
    const int wid  = tid >> 5, lane = tid & 31;
    const int v0   = blockIdx.x * 128;
    const int rsub = tid >> 3;            // 0..15
    const int chnk = tid & 7;             // 0..7
    const uint32_t st_csw = (uint32_t)((chnk * 16) ^ ((rsub & 7) << 4));

    // ---- stage tap k into buffer b ----
    auto stage = [&](int b, int k) {
        const uint32_t base = sbase + (uint32_t)b * BUFSZ;
        // A: 128 rows x 128B fp16
#pragma unroll
        for (int i = 0; i < 8; ++i) {
            const int row = rsub + i * 16;
            const int idx = nbr[(v0 + row) * KTAP + k];
            const uint32_t sz = (idx >= 0) ? 16u : 0u;
            const int ic = (idx >= 0) ? idx : 0;
            const char* s = (const char*)fh + (size_t)ic * 128 + chnk * 16;
            cpa16(base + OFF_A + (uint32_t)(row * 128) + st_csw, s, sz);
        }
        // W^T[k]: 64 rows x 128B, hi + lo
        const char* whs = (const char*)wthi + (size_t)k * 8192;
        const char* wls = (const char*)wtlo + (size_t)k * 8192;
#pragma unroll
        for (int i = 0; i < 4; ++i) {
            const int row = rsub + i * 16;            // 0..63
            const uint32_t d = base + (uint32_t)(row * 128) + st_csw;
            cpa16(d + OFF_WHI, whs + row * 128 + chnk * 16, 16);
            cpa16(d + OFF_WLO, wls + row * 128 + chnk * 16, 16);
        }
    };

    float acc[2][8][4];
#pragma unroll
    for (int mt = 0; mt < 2; ++mt)
#pragma unroll
        for (int nt = 0; nt < 8; ++nt)
#pragma unroll
            for (int r = 0; r < 4; ++r) acc[mt][nt][r] = 0.0f;

    // ldmatrix lane->address pieces (swizzled)
    const uint32_t lxor   = (uint32_t)((lane & 7) << 4);
    const uint32_t a_rowb = (uint32_t)((wid * 32 + (lane & 15)) * 128);
    const uint32_t a_colb = (uint32_t)((lane >> 4) * 16);
    const int g = lane >> 3;
    const uint32_t b_rowb = (uint32_t)((((g >> 1) * 8) + (lane & 7)) * 128);
    const uint32_t b_colb = (uint32_t)((g & 1) * 16);

    stage(0, 0);
    CPA_COMMIT();

    for (int k = 0; k < KTAP; ++k) {
        const int b = k & 1;
        if (k + 1 < KTAP) { stage(b ^ 1, k + 1); CPA_COMMIT(); CPA_WAIT1(); }
        else              { CPA_WAIT0(); }
        __syncthreads();

        const uint32_t base = sbase + (uint32_t)b * BUFSZ;
#pragma unroll
        for (int ks = 0; ks < 4; ++ks) {
            const uint32_t a_csw = (uint32_t)(ks * 32 + a_colb) ^ lxor;
            const uint32_t b_csw = (uint32_t)(ks * 32 + b_colb) ^ lxor;
            uint32_t ah[2][4];
#pragma unroll
            for (int mt = 0; mt < 2; ++mt) {
                const uint32_t aaddr = base + OFF_A + a_rowb
                                     + (uint32_t)(mt * 2048) + a_csw;
                LDSM4(ah[mt][0], ah[mt][1], ah[mt][2], ah[mt][3], aaddr);
            }
#pragma unroll
            for (int nt2 = 0; nt2 < 4; ++nt2) {
                const uint32_t baddr = base + b_rowb
                                     + (uint32_t)(nt2 * 2048) + b_csw;
                uint32_t bh[4], bl[4];
                LDSM4(bh[0], bh[1], bh[2], bh[3], baddr + OFF_WHI);
                LDSM4(bl[0], bl[1], bl[2], bl[3], baddr + OFF_WLO);
#pragma unroll
                for (int mt = 0; mt < 2; ++mt) {
                    MMA16816(acc[mt][nt2 * 2 + 0], ah[mt], bh[0], bh[1]);
                    MMA16816(acc[mt][nt2 * 2 + 1], ah[mt], bh[2], bh[3]);
                    MMA16816(acc[mt][nt2 * 2 + 0], ah[mt], bl[0], bl[1]);
                    MMA16816(acc[mt][nt2 * 2 + 1], ah[mt], bl[2], bl[3]);
                }
            }
        }
        __syncthreads();
    }

    // ---- epilogue 1: store result tile ----
    const int r0 = v0 + wid * 32 + (lane >> 2);
    const int c0 = (lane & 3) * 2;
#pragma unroll
    for (int mt = 0; mt < 2; ++mt)
#pragma unroll
        for (int nt = 0; nt < 8; ++nt) {
            float* p0 = out + (size_t)(r0 + mt * 16) * CH + nt * 8 + c0;
            float* p1 = p0 + 8 * CH;
            *reinterpret_cast<float2*>(p0) = make_float2(acc[mt][nt][0], acc[mt][nt][1]);
            *reinterpret_cast<float2*>(p1) = make_float2(acc[mt][nt][2], acc[mt][nt][3]);
        }

    // ---- epilogue 2: fused BN stats ----
    float s[8][2], q[8][2];
#pragma unroll
    for (int nt = 0; nt < 8; ++nt)
#pragma unroll
        for (int j = 0; j < 2; ++j) {
            float a0 = acc[0][nt][j],     a1 = acc[0][nt][j + 2];
            float a2 = acc[1][nt][j],     a3 = acc[1][nt][j + 2];
            s[nt][j] = (a0 + a1) + (a2 + a3);
            q[nt][j] = (a0 * a0 + a1 * a1) + (a2 * a2 + a3 * a3);
        }
#pragma unroll
    for (int st = 4; st < 32; st <<= 1)
#pragma unroll
        for (int nt = 0; nt < 8; ++nt)
#pragma unroll
            for (int j = 0; j < 2; ++j) {
                s[nt][j] += __shfl_xor_sync(0xFFFFFFFFu, s[nt][j], st);
                q[nt][j] += __shfl_xor_sync(0xFFFFFFFFu, q[nt][j], st);
            }
    float* red = reinterpret_cast<float*>(smem);     // 2KB, bufs dead
    if (lane < 4) {
#pragma unroll
        for (int nt = 0; nt < 8; ++nt)
#pragma unroll
            for (int j = 0; j < 2; ++j) {
                const int c = nt * 8 + 2 * lane + j;
                red[(wid * 2 + 0) * CH + c] = s[nt][j];
                red[(wid * 2 + 1) * CH + c] = q[nt][j];
            }
    }
    __syncthreads();
    if (tid < CH) {
        float ts = 0.0f, tq = 0.0f;
#pragma unroll
        for (int w = 0; w < 4; ++w) {
            ts += red[(w * 2 + 0) * CH + tid];
            tq += red[(w * 2 + 1) * CH + tid];
        }
        part[blockIdx.x * 128 + tid]      = ts;
        part[blockIdx.x * 128 + CH + tid] = tq;
    }
}

// ================= prep / BN / elementwise kernels =================
__global__ void tofp16_kernel(const float* __restrict__ x,
                              __half* __restrict__ xh)
{
    const int i = blockIdx.x * blockDim.x + threadIdx.x;   // float4 index
    float4 v = reinterpret_cast<const float4*>(x)[i];
    __half h[4];
    h[0] = __float2half_rn(v.x); h[1] = __float2half_rn(v.y);
    h[2] = __float2half_rn(v.z); h[3] = __float2half_rn(v.w);
    reinterpret_cast<uint2*>(xh)[i] = *reinterpret_cast<uint2*>(h);
}

// Wt[w][k][d][c] = fp16split(W_w[k][c][d])
__global__ void split_w_kernel(const float* __restrict__ W1,
                               const float* __restrict__ W2,
                               __half* __restrict__ wthi,
                               __half* __restrict__ wtlo)
{
    const int t = blockIdx.x * blockDim.x + threadIdx.x;
    const int widx = t / (KTAP * CH * CH);
    const int rem  = t % (KTAP * CH * CH);
    const int k = rem / (CH * CH);
    const int d = (rem % (CH * CH)) / CH;
    const int c = rem % CH;
    const float* W = widx ? W2 : W1;
    const float v = W[k * CH * CH + c * CH + d];
    const __half h = __float2half_rn(v);
    wthi[t] = h;
    wtlo[t] = __float2half_rn(v - __half2float(h));
}

// stage 1: 512 partial-rows -> 8 (grid=8 spreads LDG issue over 8 SMs)
__global__ void finalize1_kernel(const float* __restrict__ part,
                                 float* __restrict__ part2)
{
    __shared__ float4 sm[8][32];
    const int t  = threadIdx.x;           // 256
    const int c4 = t & 31;
    const int gp = t >> 5;
    const int row0 = blockIdx.x * 64;
    const float4* p4 = reinterpret_cast<const float4*>(part);
    float4 a = make_float4(0.f, 0.f, 0.f, 0.f);
#pragma unroll
    for (int r = gp; r < 64; r += 8) {
        float4 v = p4[(row0 + r) * 32 + c4];
        a.x += v.x; a.y += v.y; a.z += v.z; a.w += v.w;
    }
    sm[gp][c4] = a;
    __syncthreads();
    if (t < 32) {
        float4 r = make_float4(0.f, 0.f, 0.f, 0.f);
#pragma unroll
        for (int gg = 0; gg < 8; ++gg) {
            float4 v = sm[gg][t];
            r.x += v.x; r.y += v.y; r.z += v.z; r.w += v.w;
        }
        reinterpret_cast<float4*>(part2)[blockIdx.x * 32 + t] = r;
    }
}

// stage 2: combine 8 rows, fold BN affine
__global__ void finalize2_kernel(const float* __restrict__ part2,
                                 const float* __restrict__ gamma,
                                 const float* __restrict__ beta,
                                 float* __restrict__ sbuf)
{
    __shared__ float4 tot[32];
    const int t = threadIdx.x;            // 128
    if (t < 32) {
        const float4* p4 = reinterpret_cast<const float4*>(part2);
        float4 r = make_float4(0.f, 0.f, 0.f, 0.f);
#pragma unroll
        for (int g = 0; g < 8; ++g) {
            float4 v = p4[g * 32 + t];
            r.x += v.x; r.y += v.y; r.z += v.z; r.w += v.w;
        }
        tot[t] = r;
    }
    __syncthreads();
    if (t < 16) {                         // cols 0-15 sums, 16-31 sumsq
        float4 s = tot[t], q = tot[t + 16];
        const float inv_n = 1.0f / (float)NVOX;
        const float sv[4] = {s.x, s.y, s.z, s.w};
        const float qv[4] = {q.x, q.y, q.z, q.w};
#pragma unroll
        for (int e = 0; e < 4; ++e) {
            const int ch = t * 4 + e;
            const float mean = sv[e] * inv_n;
            const float var  = qv[e] * inv_n - mean * mean;
            const float sc   = gamma[ch] * rsqrtf(var + EPSV);
            sbuf[ch]      = sc;
            sbuf[CH + ch] = beta[ch] - mean * sc;
        }
    }
}

// a = relu(h*scale + bias) as fp16
__global__ void bnrelu_half_kernel(const float* __restrict__ hin,
                                   const float* __restrict__ sbuf,
                                   __half* __restrict__ ah)
{
    const int i  = blockIdx.x * blockDim.x + threadIdx.x;
    const int c0 = (i * 4) & 63;
    float4 vv = reinterpret_cast<const float4*>(hin)[i];
    float4 sc = reinterpret_cast<const float4*>(sbuf)[c0 >> 2];
    float4 bs = reinterpret_cast<const float4*>(sbuf + CH)[c0 >> 2];
    __half h[4];
    h[0] = __float2half_rn(fmaxf(fmaf(vv.x, sc.x, bs.x), 0.0f));
    h[1] = __float2half_rn(fmaxf(fmaf(vv.y, sc.y, bs.y), 0.0f));
    h[2] = __float2half_rn(fmaxf(fmaf(vv.z, sc.z, bs.z), 0.0f));
    h[3] = __float2half_rn(fmaxf(fmaf(vv.w, sc.w, bs.w), 0.0f));
    reinterpret_cast<uint2*>(ah)[i] = *reinterpret_cast<uint2*>(h);
}

// out = relu(h*scale + bias + x)
__global__ void final_kernel(const float* __restrict__ hin,
                             const float* __restrict__ sbuf,
                             const float* __restrict__ x,
                             float* __restrict__ out)
{
    const int i  = blockIdx.x * blockDim.x + threadIdx.x;
    const int c0 = (i * 4) & 63;
    float4 vv = reinterpret_cast<const float4*>(hin)[i];
    float4 xx = reinterpret_cast<const float4*>(x)[i];
    float4 sc = reinterpret_cast<const float4*>(sbuf)[c0 >> 2];
    float4 bs = reinterpret_cast<const float4*>(sbuf + CH)[c0 >> 2];
    float4 o;
    o.x = fmaxf(fmaf(vv.x, sc.x, bs.x) + xx.x, 0.0f);
    o.y = fmaxf(fmaf(vv.y, sc.y, bs.y) + xx.y, 0.0f);
    o.z = fmaxf(fmaf(vv.z, sc.z, bs.z) + xx.z, 0.0f);
    o.w = fmaxf(fmaf(vv.w, sc.w, bs.w) + xx.w, 0.0f);
    reinterpret_cast<float4*>(out)[i] = o;
}

// ================= launch =================
extern "C" void kernel_launch(void* const* d_in, const int* in_sizes, int n_in,
                              void* d_out, int out_size)
{
    const float* x   = (const float*)d_in[0];
    const int*   nbr = (const int*)  d_in[1];
    const float* W1  = (const float*)d_in[2];
    const float* ga1 = (const float*)d_in[3];
    const float* be1 = (const float*)d_in[4];
    const float* W2  = (const float*)d_in[5];
    const float* ga2 = (const float*)d_in[6];
    const float* be2 = (const float*)d_in[7];
    float* out = (float*)d_out;

    void *ph, *pxh, *pah, *pwh, *pwl, *pp, *pp2, *ps;
    cudaGetSymbolAddress(&ph,  g_h);
    cudaGetSymbolAddress(&pxh, g_xh);
    cudaGetSymbolAddress(&pah, g_ah);
    cudaGetSymbolAddress(&pwh, g_wthi);
    cudaGetSymbolAddress(&pwl, g_wtlo);
    cudaGetSymbolAddress(&pp,  g_part);
    cudaGetSymbolAddress(&pp2, g_part2);
    cudaGetSymbolAddress(&ps,  g_sb);
    float*  hbuf  = (float*)ph;
    __half* xh    = (__half*)pxh;
    __half* ah    = (__half*)pah;
    __half* wth   = (__half*)pwh;
    __half* wtl   = (__half*)pwl;
    float*  part  = (float*)pp;
    float*  part2 = (float*)pp2;
    float*  sbuf  = (float*)ps;

    cudaFuncSetAttribute(conv_mma_kernel,
                         cudaFuncAttributeMaxDynamicSharedMemorySize, SMEM_TOTAL);

    const int ew_grid = (NVOX * CH / 4) / TPB;              // 4096
    const int sw_grid = (2 * KTAP * CH * CH) / TPB;         // 864
    const int cv_grid = NVOX / 128;                         // 512
    const int WOFF    = KTAP * CH * CH;                     // 110592

    tofp16_kernel<<<ew_grid, TPB>>>(x, xh);
    split_w_kernel<<<sw_grid, TPB>>>(W1, W2, wth, wtl);

    // h1 = conv(x, W1) with fused stats; a1 = relu(bn1(h1)) as fp16
    conv_mma_kernel<<<cv_grid, 128, SMEM_TOTAL>>>(xh, nbr, wth, wtl, hbuf, part);
    finalize1_kernel<<<8, TPB>>>(part, part2);
    finalize2_kernel<<<1, 128>>>(part2, ga1, be1, sbuf);
    bnrelu_half_kernel<<<ew_grid, TPB>>>(hbuf, sbuf, ah);

    // h2 = conv(a1, W2) with fused stats; out = relu(bn2(h2) + x)
    conv_mma_kernel<<<cv_grid, 128, SMEM_TOTAL>>>(ah, nbr, wth + WOFF, wtl + WOFF, hbuf, part);
    finalize1_kernel<<<8, TPB>>>(part, part2);
    finalize2_kernel<<<1, 128>>>(part2, ga2, be2, sbuf);
    final_kernel<<<ew_grid, TPB>>>(hbuf, sbuf, x, out);
}

// round 12
// speedup vs baseline: 9.3421x; 1.5434x over previous
#include <cuda_runtime.h>
#include <cuda_fp16.h>
#include <stdint.h>

#define NVOX 65536
#define KTAP 27
#define CH   64
#define TPB  256
#define EPSV 1e-5f

// ---- SMEM per pipeline buffer: A(fp16) 16KB | W(fp16) 8KB ----
#define OFF_A   0
#define OFF_W   16384
#define BUFSZ   24576
#define SMEM_TOTAL (2 * BUFSZ)     // 49152 B -> 4 CTAs/SM

// ---------------- scratch (no allocations allowed) ----------------
__device__ float   g_h[NVOX * CH];               // conv output (fp32)
__device__ __half  g_xh[NVOX * CH];              // x as fp16
__device__ __half  g_ah[NVOX * CH];              // activations as fp16
__device__ __half  g_wt[2 * KTAP * CH * CH];     // W^T fp16: [w][k][d][c]
__device__ float   g_part[512 * 2 * CH];         // per-conv-CTA {sum, sumsq}[64]
__device__ float   g_part2[8 * 2 * CH];          // stage-1 reduced partials
__device__ float   g_sb[2 * CH];                 // folded BN affine

// ================= PTX helpers =================
__device__ __forceinline__ uint32_t smem_u32(const void* p) {
    uint32_t a;
    asm("{ .reg .u64 t; cvta.to.shared.u64 t, %1; cvt.u32.u64 %0, t; }"
        : "=r"(a) : "l"(p));
    return a;
}
__device__ __forceinline__ void cpa16(uint32_t dst, const void* src, uint32_t srcsz) {
    asm volatile("cp.async.ca.shared.global [%0], [%1], 16, %2;"
                 :: "r"(dst), "l"(src), "r"(srcsz) : "memory");
}
#define CPA_COMMIT() asm volatile("cp.async.commit_group;" ::: "memory")
#define CPA_WAIT1()  asm volatile("cp.async.wait_group 1;" ::: "memory")
#define CPA_WAIT0()  asm volatile("cp.async.wait_group 0;" ::: "memory")

#define LDSM4(r0, r1, r2, r3, addr) \
    asm volatile("ldmatrix.sync.aligned.m8n8.x4.shared.b16 {%0,%1,%2,%3}, [%4];" \
                 : "=r"(r0), "=r"(r1), "=r"(r2), "=r"(r3) : "r"(addr))

#define MMA16816(c, a, b0, b1) \
    asm volatile("mma.sync.aligned.m16n8k16.row.col.f32.f16.f16.f32 " \
                 "{%0,%1,%2,%3}, {%4,%5,%6,%7}, {%8,%9}, {%0,%1,%2,%3};" \
                 : "+f"((c)[0]), "+f"((c)[1]), "+f"((c)[2]), "+f"((c)[3]) \
                 : "r"((a)[0]), "r"((a)[1]), "r"((a)[2]), "r"((a)[3]), \
                   "r"(b0), "r"(b1))

// ================= conv via mma.sync fp16 (single product) =================
// CTA: 128 threads / 4 warps, one 128-voxel tile, full N=64; 4 CTAs/SM.
// A and W both fp16-RN (per-element rel err <= 2^-11; random-sign cancellation
// over the 1728-term reduction keeps output err ~3-5e-4, BN absorbs per-channel
// scale). D += A*W. SW128 swizzle: (row, col) -> row*128 + (col ^ ((row&7)<<4)).
// Epilogue fuses BN stats into deterministic per-block partials.
__global__ void __launch_bounds__(128, 4)
conv_mma_kernel(const __half* __restrict__ fh,
                const int* __restrict__ nbr,
                const __half* __restrict__ wt,
                float* __restrict__ out,
                float* __restrict__ part)
{
    extern __shared__ char smem[];
    const uint32_t sbase = smem_u32(smem);
    const int tid  = threadIdx.x;
    const int wid  = tid >> 5, lane = tid & 31;
    const int v0   = blockIdx.x * 128;
    const int rsub = tid >> 3;            // 0..15
    const int chnk = tid & 7;             // 0..7
    const uint32_t st_csw = (uint32_t)((chnk * 16) ^ ((rsub & 7) << 4));

    // ---- stage tap k into buffer b ----
    auto stage = [&](int b, int k) {
        const uint32_t base = sbase + (uint32_t)b * BUFSZ;
        // A: 128 rows x 128B fp16 (zfill inactive taps)
#pragma unroll
        for (int i = 0; i < 8; ++i) {
            const int row = rsub + i * 16;
            const int idx = nbr[(v0 + row) * KTAP + k];
            const uint32_t sz = (idx >= 0) ? 16u : 0u;
            const int ic = (idx >= 0) ? idx : 0;
            const char* s = (const char*)fh + (size_t)ic * 128 + chnk * 16;
            cpa16(base + OFF_A + (uint32_t)(row * 128) + st_csw, s, sz);
        }
        // W^T[k]: 64 rows x 128B
        const char* ws = (const char*)wt + (size_t)k * 8192;
#pragma unroll
        for (int i = 0; i < 4; ++i) {
            const int row = rsub + i * 16;            // 0..63
            cpa16(base + OFF_W + (uint32_t)(row * 128) + st_csw,
                  ws + row * 128 + chnk * 16, 16);
        }
    };

    float acc[2][8][4];
#pragma unroll
    for (int mt = 0; mt < 2; ++mt)
#pragma unroll
        for (int nt = 0; nt < 8; ++nt)
#pragma unroll
            for (int r = 0; r < 4; ++r) acc[mt][nt][r] = 0.0f;

    // ldmatrix lane->address pieces (swizzled)
    const uint32_t lxor   = (uint32_t)((lane & 7) << 4);
    const uint32_t a_rowb = (uint32_t)((wid * 32 + (lane & 15)) * 128);
    const uint32_t a_colb = (uint32_t)((lane >> 4) * 16);
    const int g = lane >> 3;
    const uint32_t b_rowb = (uint32_t)((((g >> 1) * 8) + (lane & 7)) * 128);
    const uint32_t b_colb = (uint32_t)((g & 1) * 16);

    stage(0, 0);
    CPA_COMMIT();

    for (int k = 0; k < KTAP; ++k) {
        const int b = k & 1;
        if (k + 1 < KTAP) { stage(b ^ 1, k + 1); CPA_COMMIT(); CPA_WAIT1(); }
        else              { CPA_WAIT0(); }
        __syncthreads();

        const uint32_t base = sbase + (uint32_t)b * BUFSZ;
#pragma unroll
        for (int ks = 0; ks < 4; ++ks) {
            const uint32_t a_csw = (uint32_t)(ks * 32 + a_colb) ^ lxor;
            const uint32_t b_csw = (uint32_t)(ks * 32 + b_colb) ^ lxor;
            uint32_t ah[2][4];
#pragma unroll
            for (int mt = 0; mt < 2; ++mt) {
                const uint32_t aaddr = base + OFF_A + a_rowb
                                     + (uint32_t)(mt * 2048) + a_csw;
                LDSM4(ah[mt][0], ah[mt][1], ah[mt][2], ah[mt][3], aaddr);
            }
#pragma unroll
            for (int nt2 = 0; nt2 < 4; ++nt2) {
                const uint32_t baddr = base + OFF_W + b_rowb
                                     + (uint32_t)(nt2 * 2048) + b_csw;
                uint32_t bh[4];
                LDSM4(bh[0], bh[1], bh[2], bh[3], baddr);
#pragma unroll
                for (int mt = 0; mt < 2; ++mt) {
                    MMA16816(acc[mt][nt2 * 2 + 0], ah[mt], bh[0], bh[1]);
                    MMA16816(acc[mt][nt2 * 2 + 1], ah[mt], bh[2], bh[3]);
                }
            }
        }
        __syncthreads();
    }

    // ---- epilogue 1: store result tile ----
    const int r0 = v0 + wid * 32 + (lane >> 2);
    const int c0 = (lane & 3) * 2;
#pragma unroll
    for (int mt = 0; mt < 2; ++mt)
#pragma unroll
        for (int nt = 0; nt < 8; ++nt) {
            float* p0 = out + (size_t)(r0 + mt * 16) * CH + nt * 8 + c0;
            float* p1 = p0 + 8 * CH;
            *reinterpret_cast<float2*>(p0) = make_float2(acc[mt][nt][0], acc[mt][nt][1]);
            *reinterpret_cast<float2*>(p1) = make_float2(acc[mt][nt][2], acc[mt][nt][3]);
        }

    // ---- epilogue 2: fused BN stats ----
    float s[8][2], q[8][2];
#pragma unroll
    for (int nt = 0; nt < 8; ++nt)
#pragma unroll
        for (int j = 0; j < 2; ++j) {
            float a0 = acc[0][nt][j],     a1 = acc[0][nt][j + 2];
            float a2 = acc[1][nt][j],     a3 = acc[1][nt][j + 2];
            s[nt][j] = (a0 + a1) + (a2 + a3);
            q[nt][j] = (a0 * a0 + a1 * a1) + (a2 * a2 + a3 * a3);
        }
#pragma unroll
    for (int st = 4; st < 32; st <<= 1)
#pragma unroll
        for (int nt = 0; nt < 8; ++nt)
#pragma unroll
            for (int j = 0; j < 2; ++j) {
                s[nt][j] += __shfl_xor_sync(0xFFFFFFFFu, s[nt][j], st);
                q[nt][j] += __shfl_xor_sync(0xFFFFFFFFu, q[nt][j], st);
            }
    float* red = reinterpret_cast<float*>(smem);     // 2KB, bufs dead
    if (lane < 4) {
#pragma unroll
        for (int nt = 0; nt < 8; ++nt)
#pragma unroll
            for (int j = 0; j < 2; ++j) {
                const int c = nt * 8 + 2 * lane + j;
                red[(wid * 2 + 0) * CH + c] = s[nt][j];
                red[(wid * 2 + 1) * CH + c] = q[nt][j];
            }
    }
    __syncthreads();
    if (tid < CH) {
        float ts = 0.0f, tq = 0.0f;
#pragma unroll
        for (int w = 0; w < 4; ++w) {
            ts += red[(w * 2 + 0) * CH + tid];
            tq += red[(w * 2 + 1) * CH + tid];
        }
        part[blockIdx.x * 128 + tid]      = ts;
        part[blockIdx.x * 128 + CH + tid] = tq;
    }
}

// ================= prep / BN / elementwise kernels =================
__global__ void tofp16_kernel(const float* __restrict__ x,
                              __half* __restrict__ xh)
{
    const int i = blockIdx.x * blockDim.x + threadIdx.x;   // float4 index
    float4 v = reinterpret_cast<const float4*>(x)[i];
    __half h[4];
    h[0] = __float2half_rn(v.x); h[1] = __float2half_rn(v.y);
    h[2] = __float2half_rn(v.z); h[3] = __float2half_rn(v.w);
    reinterpret_cast<uint2*>(xh)[i] = *reinterpret_cast<uint2*>(h);
}

// Wt[w][k][d][c] = fp16(W_w[k][c][d])
__global__ void conv_w_kernel(const float* __restrict__ W1,
                              const float* __restrict__ W2,
                              __half* __restrict__ wt)
{
    const int t = blockIdx.x * blockDim.x + threadIdx.x;
    const int widx = t / (KTAP * CH * CH);
    const int rem  = t % (KTAP * CH * CH);
    const int k = rem / (CH * CH);
    const int d = (rem % (CH * CH)) / CH;
    const int c = rem % CH;
    const float* W = widx ? W2 : W1;
    wt[t] = __float2half_rn(W[k * CH * CH + c * CH + d]);
}

// stage 1: 512 partial-rows -> 8 (grid=8 spreads LDG issue over 8 SMs)
__global__ void finalize1_kernel(const float* __restrict__ part,
                                 float* __restrict__ part2)
{
    __shared__ float4 sm[8][32];
    const int t  = threadIdx.x;           // 256
    const int c4 = t & 31;
    const int gp = t >> 5;
    const int row0 = blockIdx.x * 64;
    const float4* p4 = reinterpret_cast<const float4*>(part);
    float4 a = make_float4(0.f, 0.f, 0.f, 0.f);
#pragma unroll
    for (int r = gp; r < 64; r += 8) {
        float4 v = p4[(row0 + r) * 32 + c4];
        a.x += v.x; a.y += v.y; a.z += v.z; a.w += v.w;
    }
    sm[gp][c4] = a;
    __syncthreads();
    if (t < 32) {
        float4 r = make_float4(0.f, 0.f, 0.f, 0.f);
#pragma unroll
        for (int gg = 0; gg < 8; ++gg) {
            float4 v = sm[gg][t];
            r.x += v.x; r.y += v.y; r.z += v.z; r.w += v.w;
        }
        reinterpret_cast<float4*>(part2)[blockIdx.x * 32 + t] = r;
    }
}

// stage 2: combine 8 rows, fold BN affine
__global__ void finalize2_kernel(const float* __restrict__ part2,
                                 const float* __restrict__ gamma,
                                 const float* __restrict__ beta,
                                 float* __restrict__ sbuf)
{
    __shared__ float4 tot[32];
    const int t = threadIdx.x;            // 128
    if (t < 32) {
        const float4* p4 = reinterpret_cast<const float4*>(part2);
        float4 r = make_float4(0.f, 0.f, 0.f, 0.f);
#pragma unroll
        for (int g = 0; g < 8; ++g) {
            float4 v = p4[g * 32 + t];
            r.x += v.x; r.y += v.y; r.z += v.z; r.w += v.w;
        }
        tot[t] = r;
    }
    __syncthreads();
    if (t < 16) {                         // cols 0-15 sums, 16-31 sumsq
        float4 s = tot[t], q = tot[t + 16];
        const float inv_n = 1.0f / (float)NVOX;
        const float sv[4] = {s.x, s.y, s.z, s.w};
        const float qv[4] = {q.x, q.y, q.z, q.w};
#pragma unroll
        for (int e = 0; e < 4; ++e) {
            const int ch = t * 4 + e;
            const float mean = sv[e] * inv_n;
            const float var  = qv[e] * inv_n - mean * mean;
            const float sc   = gamma[ch] * rsqrtf(var + EPSV);
            sbuf[ch]      = sc;
            sbuf[CH + ch] = beta[ch] - mean * sc;
        }
    }
}

// a = relu(h*scale + bias) as fp16
__global__ void bnrelu_half_kernel(const float* __restrict__ hin,
                                   const float* __restrict__ sbuf,
                                   __half* __restrict__ ah)
{
    const int i  = blockIdx.x * blockDim.x + threadIdx.x;
    const int c0 = (i * 4) & 63;
    float4 vv = reinterpret_cast<const float4*>(hin)[i];
    float4 sc = reinterpret_cast<const float4*>(sbuf)[c0 >> 2];
    float4 bs = reinterpret_cast<const float4*>(sbuf + CH)[c0 >> 2];
    __half h[4];
    h[0] = __float2half_rn(fmaxf(fmaf(vv.x, sc.x, bs.x), 0.0f));
    h[1] = __float2half_rn(fmaxf(fmaf(vv.y, sc.y, bs.y), 0.0f));
    h[2] = __float2half_rn(fmaxf(fmaf(vv.z, sc.z, bs.z), 0.0f));
    h[3] = __float2half_rn(fmaxf(fmaf(vv.w, sc.w, bs.w), 0.0f));
    reinterpret_cast<uint2*>(ah)[i] = *reinterpret_cast<uint2*>(h);
}

// out = relu(h*scale + bias + x)
__global__ void final_kernel(const float* __restrict__ hin,
                             const float* __restrict__ sbuf,
                             const float* __restrict__ x,
                             float* __restrict__ out)
{
    const int i  = blockIdx.x * blockDim.x + threadIdx.x;
    const int c0 = (i * 4) & 63;
    float4 vv = reinterpret_cast<const float4*>(hin)[i];
    float4 xx = reinterpret_cast<const float4*>(x)[i];
    float4 sc = reinterpret_cast<const float4*>(sbuf)[c0 >> 2];
    float4 bs = reinterpret_cast<const float4*>(sbuf + CH)[c0 >> 2];
    float4 o;
    o.x = fmaxf(fmaf(vv.x, sc.x, bs.x) + xx.x, 0.0f);
    o.y = fmaxf(fmaf(vv.y, sc.y, bs.y) + xx.y, 0.0f);
    o.z = fmaxf(fmaf(vv.z, sc.z, bs.z) + xx.z, 0.0f);
    o.w = fmaxf(fmaf(vv.w, sc.w, bs.w) + xx.w, 0.0f);
    reinterpret_cast<float4*>(out)[i] = o;
}

// ================= launch =================
extern "C" void kernel_launch(void* const* d_in, const int* in_sizes, int n_in,
                              void* d_out, int out_size)
{
    const float* x   = (const float*)d_in[0];
    const int*   nbr = (const int*)  d_in[1];
    const float* W1  = (const float*)d_in[2];
    const float* ga1 = (const float*)d_in[3];
    const float* be1 = (const float*)d_in[4];
    const float* W2  = (const float*)d_in[5];
    const float* ga2 = (const float*)d_in[6];
    const float* be2 = (const float*)d_in[7];
    float* out = (float*)d_out;

    void *ph, *pxh, *pah, *pw, *pp, *pp2, *ps;
    cudaGetSymbolAddress(&ph,  g_h);
    cudaGetSymbolAddress(&pxh, g_xh);
    cudaGetSymbolAddress(&pah, g_ah);
    cudaGetSymbolAddress(&pw,  g_wt);
    cudaGetSymbolAddress(&pp,  g_part);
    cudaGetSymbolAddress(&pp2, g_part2);
    cudaGetSymbolAddress(&ps,  g_sb);
    float*  hbuf  = (float*)ph;
    __half* xh    = (__half*)pxh;
    __half* ah    = (__half*)pah;
    __half* wt    = (__half*)pw;
    float*  part  = (float*)pp;
    float*  part2 = (float*)pp2;
    float*  sbuf  = (float*)ps;

    cudaFuncSetAttribute(conv_mma_kernel,
                         cudaFuncAttributeMaxDynamicSharedMemorySize, SMEM_TOTAL);

    const int ew_grid = (NVOX * CH / 4) / TPB;              // 4096
    const int sw_grid = (2 * KTAP * CH * CH) / TPB;         // 864
    const int cv_grid = NVOX / 128;                         // 512
    const int WOFF    = KTAP * CH * CH;                     // 110592

    tofp16_kernel<<<ew_grid, TPB>>>(x, xh);
    conv_w_kernel<<<sw_grid, TPB>>>(W1, W2, wt);

    // h1 = conv(x, W1) with fused stats; a1 = relu(bn1(h1)) as fp16
    conv_mma_kernel<<<cv_grid, 128, SMEM_TOTAL>>>(xh, nbr, wt, hbuf, part);
    finalize1_kernel<<<8, TPB>>>(part, part2);
    finalize2_kernel<<<1, 128>>>(part2, ga1, be1, sbuf);
    bnrelu_half_kernel<<<ew_grid, TPB>>>(hbuf, sbuf, ah);

    // h2 = conv(a1, W2) with fused stats; out = relu(bn2(h2) + x)
    conv_mma_kernel<<<cv_grid, 128, SMEM_TOTAL>>>(ah, nbr, wt + WOFF, hbuf, part);
    finalize1_kernel<<<8, TPB>>>(part, part2);
    finalize2_kernel<<<1, 128>>>(part2, ga2, be2, sbuf);
    final_kernel<<<ew_grid, TPB>>>(hbuf, sbuf, x, out);
}